// round 7
// baseline (speedup 1.0000x reference)
#include <cuda_runtime.h>
#include <cuda_fp16.h>
#include <cstdint>

#define N_NODES 4096
#define NS 128
#define NV 16
#define H 8
#define D 16
#define COMB 144
#define HD 128   // H*D

typedef unsigned long long u64;

// ---- packed f32x2 helpers (proj/out GEMVs) ----
__device__ __forceinline__ u64 pack2(float lo, float hi) {
    u64 d; asm("mov.b64 %0, {%1, %2};" : "=l"(d) : "f"(lo), "f"(hi)); return d;
}
__device__ __forceinline__ void unpack2(u64 x, float& lo, float& hi) {
    asm("mov.b64 {%0, %1}, %2;" : "=f"(lo), "=f"(hi) : "l"(x));
}
__device__ __forceinline__ u64 fma2(u64 a, u64 b, u64 c) {
    u64 d; asm("fma.rn.f32x2 %0, %1, %2, %3;" : "=l"(d) : "l"(a), "l"(b), "l"(c)); return d;
}
// ---- f16 mma, fp32 accumulate (PV) ----
__device__ __forceinline__ void mma_f16(float* d, const uint32_t* a, uint32_t b0, uint32_t b1) {
    asm("mma.sync.aligned.m16n8k16.row.col.f32.f16.f16.f32 "
        "{%0,%1,%2,%3},{%4,%5,%6,%7},{%8,%9},{%0,%1,%2,%3};"
        : "+f"(d[0]), "+f"(d[1]), "+f"(d[2]), "+f"(d[3])
        : "r"(a[0]), "r"(a[1]), "r"(a[2]), "r"(a[3]), "r"(b0), "r"(b1));
}
// ---- f16 mma, f16 accumulate (S scores; D packed f16x2 = exp input) ----
__device__ __forceinline__ void mma_f16_s(uint32_t& d0, uint32_t& d1, const uint32_t* a,
                                          uint32_t b0, uint32_t b1) {
    asm("mma.sync.aligned.m16n8k16.row.col.f16.f16.f16.f16 "
        "{%0,%1},{%2,%3,%4,%5},{%6,%7},{%8,%9};"
        : "=r"(d0), "=r"(d1)
        : "r"(a[0]), "r"(a[1]), "r"(a[2]), "r"(a[3]), "r"(b0), "r"(b1),
          "r"(0u), "r"(0u));
}
__device__ __forceinline__ uint32_t h2bits(__half2 h) {
    return *reinterpret_cast<uint32_t*>(&h);
}
__device__ __forceinline__ __half2 bits2h(uint32_t u) {
    return *reinterpret_cast<__half2*>(&u);
}
// ---- cp.async helpers ----
__device__ __forceinline__ void cp16(void* smem_dst, const void* gsrc) {
    uint32_t d = (uint32_t)__cvta_generic_to_shared(smem_dst);
    asm volatile("cp.async.cg.shared.global [%0], [%1], 16;" :: "r"(d), "l"(gsrc));
}
__device__ __forceinline__ void cp_commit() {
    asm volatile("cp.async.commit_group;");
}
template <int N>
__device__ __forceinline__ void cp_wait() {
    asm volatile("cp.async.wait_group %0;" :: "n"(N) : "memory");
}
__device__ __forceinline__ void barx(int id) {   // 128-thread named barrier
    asm volatile("bar.sync %0, 128;" :: "r"(id) : "memory");
}

// Scratch (static device globals — no allocation allowed)
__device__ __half g_qh[N_NODES * HD];   // q * (D^-0.5 * log2e), f16, [node][ch]
__device__ __half g_kh[N_NODES * HD];   // k, f16, [node][ch]
__device__ __half g_vth[HD * N_NODES];  // v, f16, TRANSPOSED [ch][node]
__device__ float  g_attn[N_NODES * HD];

// ---------------------------------------------------------------------------
// Kernel 1: projections. 8 nodes/block, 256 threads: warp-group 0 computes
// q (and v for nodes 0-3), group 1 computes k (and v for nodes 4-7).
// Weight tiles double-buffered via cp.async.
// ---------------------------------------------------------------------------
#define PNODES 8
__global__ void proj_kernel(const float* __restrict__ s, const float* __restrict__ v,
                            const float* __restrict__ Wq, const float* __restrict__ bq,
                            const float* __restrict__ Wk, const float* __restrict__ bk,
                            const float* __restrict__ Wv, const float* __restrict__ bv) {
    const int nb = blockIdx.x * PNODES;
    const int t = threadIdx.x;       // 0..255
    const int grp = t >> 7;          // 0: q-side, 1: k-side
    const int tc = t & 127;          // output channel
    __shared__ __align__(16) float comb_t[COMB][PNODES];
    __shared__ __align__(16) float wsm[2][2][16 * 128];   // [buf][array][tile]

    for (int idx = t; idx < COMB * PNODES; idx += 256) {
        const int j = idx & 7;
        const int i = idx >> 3;
        float val;
        if (i < NS) {
            val = s[(nb + j) * NS + i];
        } else {
            const int vi = i - NS;
            const float* vp = &v[(nb + j) * NV * 3 + vi * 3];
            float x = vp[0], y = vp[1], z = vp[2];
            val = sqrtf(fmaxf(x * x + y * y + z * z, 1e-8f));
        }
        comb_t[i][j] = val;
    }

    const float bb = grp ? bk[tc] : bq[tc];
    const float bvv = bv[tc];
    u64 acc[4], av[2];
#pragma unroll
    for (int jj = 0; jj < 4; jj++) acc[jj] = pack2(bb, bb);
    av[0] = pack2(bvv, bvv); av[1] = av[0];

    // ---- Phase A: Wq (grp0) / Wk (grp1) over COMB=144, 9 tiles ----
    {
#pragma unroll
        for (int p = 0; p < 2; p++) {
            cp16(&((float4*)wsm[0][0])[t + p * 256], (const float4*)Wq + t + p * 256);
            cp16(&((float4*)wsm[0][1])[t + p * 256], (const float4*)Wk + t + p * 256);
        }
        cp_commit();
        for (int kt = 0; kt < 9; kt++) {
            if (kt < 8) {
                const int nbuf = (kt + 1) & 1;
                const float4* sq4 = (const float4*)(Wq + (kt + 1) * 2048);
                const float4* sk4 = (const float4*)(Wk + (kt + 1) * 2048);
#pragma unroll
                for (int p = 0; p < 2; p++) {
                    cp16(&((float4*)wsm[nbuf][0])[t + p * 256], sq4 + t + p * 256);
                    cp16(&((float4*)wsm[nbuf][1])[t + p * 256], sk4 + t + p * 256);
                }
                cp_commit();
                cp_wait<1>();
            } else {
                cp_wait<0>();
            }
            __syncthreads();
            const int b = kt & 1;
            const float* wcol = wsm[b][grp];
#pragma unroll
            for (int ii = 0; ii < 16; ii++) {
                const int i = kt * 16 + ii;
                const float w = wcol[ii * 128 + tc];
                const u64 w2 = pack2(w, w);
                const ulonglong2* cr = (const ulonglong2*)comb_t[i];
                const ulonglong2 ca = cr[0], cb = cr[1];
                acc[0] = fma2(w2, ca.x, acc[0]); acc[1] = fma2(w2, ca.y, acc[1]);
                acc[2] = fma2(w2, cb.x, acc[2]); acc[3] = fma2(w2, cb.y, acc[3]);
            }
            __syncthreads();
        }
    }
    // ---- Phase B: Wv over NS=128 (8 tiles); node-split across groups ----
    {
#pragma unroll
        for (int p = 0; p < 2; p++)
            cp16(&((float4*)wsm[0][0])[t + p * 256], (const float4*)Wv + t + p * 256);
        cp_commit();
        for (int kt = 0; kt < 8; kt++) {
            if (kt < 7) {
                const int nbuf = (kt + 1) & 1;
                const float4* sv4 = (const float4*)(Wv + (kt + 1) * 2048);
#pragma unroll
                for (int p = 0; p < 2; p++)
                    cp16(&((float4*)wsm[nbuf][0])[t + p * 256], sv4 + t + p * 256);
                cp_commit();
                cp_wait<1>();
            } else {
                cp_wait<0>();
            }
            __syncthreads();
            const int b = kt & 1;
#pragma unroll
            for (int ii = 0; ii < 16; ii++) {
                const int i = kt * 16 + ii;
                const float w = wsm[b][0][ii * 128 + tc];
                const u64 w2 = pack2(w, w);
                const ulonglong2 cc = ((const ulonglong2*)comb_t[i])[grp];
                av[0] = fma2(w2, cc.x, av[0]);
                av[1] = fma2(w2, cc.y, av[1]);
            }
            __syncthreads();
        }
    }

    const float CS = 0.25f * 1.4426950408889634f;  // D^-0.5 * log2(e), folded into q
    const float sc = grp ? 1.f : CS;
    __half* dst = grp ? g_kh : g_qh;
#pragma unroll
    for (int jj = 0; jj < 4; jj++) {
        float lo, hi;
        unpack2(acc[jj], lo, hi);
        dst[(nb + 2 * jj) * HD + tc]     = __float2half(lo * sc);
        dst[(nb + 2 * jj + 1) * HD + tc] = __float2half(hi * sc);
    }
#pragma unroll
    for (int jj = 0; jj < 2; jj++) {
        float lo, hi;
        unpack2(av[jj], lo, hi);
        const int node = nb + grp * 4 + 2 * jj;
        g_vth[tc * N_NODES + node]     = __float2half(lo);
        g_vth[tc * N_NODES + node + 1] = __float2half(hi);
    }
}

// ---------------------------------------------------------------------------
// Kernel 2: f16 tensor-core flash attention. 8 warps/block, in-block split-K.
//  - S-mma in f16 ACCUMULATION: D regs are packed f16x2 pairs -> h2exp2
//    input directly (no cvt), and half the MMA-pipe cost of f32-acc.
//  - No ones-MMA: row sums via HADD2 (f16, per-128-key-tile partial, safe
//    range <= ~1k) flushed to fp32 each tile.
//  - PV MMA stays fp32-accumulate (4096-term sums).
// ---------------------------------------------------------------------------
__global__ void attn_kernel() {
    const int h = blockIdx.y;
    const int qbase = blockIdx.x * 64;
    const int gid = threadIdx.x >> 7;   // key-split group 0/1
    const int tl = threadIdx.x & 127;
    const int w = tl >> 5;
    const int lane = tl & 31;
    const int g = lane >> 2;
    const int tid = lane & 3;

    __shared__ __align__(16) uint32_t Ksw[2][128 * 12];
    __shared__ __align__(16) uint32_t Vsw[2][16 * 68];
    __shared__ float mrg[128][10];

    uint32_t qa[4];
    {
        const __half* Q0 = g_qh + (qbase + w * 16 + g) * HD + h * D;
        const __half* Q1 = Q0 + 8 * HD;
        qa[0] = *(const uint32_t*)(Q0 + 2 * tid);
        qa[1] = *(const uint32_t*)(Q1 + 2 * tid);
        qa[2] = *(const uint32_t*)(Q0 + 2 * tid + 8);
        qa[3] = *(const uint32_t*)(Q1 + 2 * tid + 8);
    }

    float o0[4] = {0.f, 0.f, 0.f, 0.f};
    float o1[4] = {0.f, 0.f, 0.f, 0.f};
    float l0 = 0.f, l1 = 0.f;

    const int vrow = tl & 15;
    const int vchunk = tl >> 4;
    uint32_t* Kg = Ksw[gid];
    uint32_t* Vg = Vsw[gid];

    for (int i = 0; i < 16; i++) {
        const int kt = (2 * i + gid) * 128;
        barx(1 + gid);
        {
            const uint4* kp = (const uint4*)(g_kh + (kt + tl) * HD + h * D);
            uint4* kd = (uint4*)(Kg + tl * 12);
            kd[0] = kp[0];
            kd[1] = kp[1];
            const uint4* vp = (const uint4*)(g_vth + (h * D + vrow) * N_NODES + kt + vchunk * 16);
            uint4* vd = (uint4*)(Vg + vrow * 68 + vchunk * 8);
            vd[0] = vp[0];
            vd[1] = vp[1];
        }
        barx(1 + gid);

        __half2 lh0 = __half2half2(__float2half(0.f));
        __half2 lh1 = lh0;
#pragma unroll
        for (int u = 0; u < 8; u++) {       // 16 keys
            uint32_t sA0, sA1, sB0, sB1;
            const int kA = (16 * u + g) * 12;
            const int kB = (16 * u + 8 + g) * 12;
            mma_f16_s(sA0, sA1, qa, Kg[kA + tid], Kg[kA + 4 + tid]);
            mma_f16_s(sB0, sB1, qa, Kg[kB + tid], Kg[kB + 4 + tid]);
            // p = 2^S, packed f16x2 pairs: directly the PV A-fragment
            const __half2 e0 = h2exp2(bits2h(sA0));  // row g,   k 2tid,2tid+1
            const __half2 e1 = h2exp2(bits2h(sA1));  // row g+8, k 2tid,2tid+1
            const __half2 e2 = h2exp2(bits2h(sB0));  // row g,   k 8+2tid pair
            const __half2 e3 = h2exp2(bits2h(sB1));  // row g+8
            lh0 = __hadd2(lh0, __hadd2(e0, e2));
            lh1 = __hadd2(lh1, __hadd2(e1, e3));
            uint32_t pa[4];
            pa[0] = h2bits(e0);
            pa[1] = h2bits(e1);
            pa[2] = h2bits(e2);
            pa[3] = h2bits(e3);
            const int vb = 8 * u + tid;
            mma_f16(o0, pa, Vg[g * 68 + vb],       Vg[g * 68 + 4 + vb]);
            mma_f16(o1, pa, Vg[(g + 8) * 68 + vb], Vg[(g + 8) * 68 + 4 + vb]);
        }
        // flush f16 tile-partials into fp32 totals
        const float2 f0 = __half22float2(lh0);
        const float2 f1 = __half22float2(lh1);
        l0 += f0.x + f0.y;
        l1 += f1.x + f1.y;
    }

    // quad-reduce row sums (each thread holds 4 of the 16 key-columns)
    l0 += __shfl_xor_sync(0xffffffffu, l0, 1);
    l0 += __shfl_xor_sync(0xffffffffu, l0, 2);
    l1 += __shfl_xor_sync(0xffffffffu, l1, 1);
    l1 += __shfl_xor_sync(0xffffffffu, l1, 2);

    // merge split-K partials (fp32) through smem
    if (gid == 1) {
        float* m = mrg[tl];
        m[0] = o0[0]; m[1] = o0[1]; m[2] = o0[2]; m[3] = o0[3];
        m[4] = o1[0]; m[5] = o1[1]; m[6] = o1[2]; m[7] = o1[3];
        m[8] = l0; m[9] = l1;
    }
    __syncthreads();
    if (gid == 0) {
        const float* m = mrg[tl];
        const float i0 = 1.f / (l0 + m[8]);
        const float i1 = 1.f / (l1 + m[9]);
        float* O0 = &g_attn[(qbase + w * 16 + g) * HD + h * D];
        float* O1 = O0 + 8 * HD;
        *(float2*)&O0[2 * tid]     = make_float2((o0[0] + m[0]) * i0, (o0[1] + m[1]) * i0);
        *(float2*)&O1[2 * tid]     = make_float2((o0[2] + m[2]) * i1, (o0[3] + m[3]) * i1);
        *(float2*)&O0[2 * tid + 8] = make_float2((o1[0] + m[4]) * i0, (o1[1] + m[5]) * i0);
        *(float2*)&O1[2 * tid + 8] = make_float2((o1[2] + m[6]) * i1, (o1[3] + m[7]) * i1);
    }
}

// ---------------------------------------------------------------------------
// Kernel 3: out proj + residual + LayerNorm + v passthrough.
// 8 nodes/block, 256 threads; node-split accumulation across warp-groups.
// ---------------------------------------------------------------------------
#define ONODES 8
__global__ void out_kernel(const float* __restrict__ s, const float* __restrict__ vin,
                           const float* __restrict__ Wo, const float* __restrict__ bo,
                           const float* __restrict__ gamma, const float* __restrict__ beta,
                           float* __restrict__ out) {
    const int nb = blockIdx.x * ONODES;
    const int t = threadIdx.x;       // 0..255
    const int grp = t >> 7;
    const int tc = t & 127;
    const int w = t >> 5;
    const int lane = t & 31;
    __shared__ __align__(16) float a_t[HD][ONODES];
    __shared__ __align__(16) float wsm[2][16 * 128];
    __shared__ float vals[ONODES][128];
    __shared__ float mus[ONODES], ivs[ONODES];

    // v passthrough: 96 float4 per block
    {
        const float4* vsrc = (const float4*)vin + blockIdx.x * 96;
        float4* vdst = (float4*)(out + N_NODES * NS) + blockIdx.x * 96;
        if (t < 96) vdst[t] = vsrc[t];
    }

    for (int idx = t; idx < HD * ONODES; idx += 256) {
        const int j = idx & 7;
        const int i = idx >> 3;
        a_t[i][j] = g_attn[(nb + j) * HD + i];
    }

    const float bov = bo[tc];
    u64 acc[2];
    acc[0] = pack2(bov, bov);
    acc[1] = acc[0];

#pragma unroll
    for (int p = 0; p < 2; p++)
        cp16(&((float4*)wsm[0])[t + p * 256], (const float4*)Wo + t + p * 256);
    cp_commit();
    for (int kt = 0; kt < 8; kt++) {
        if (kt < 7) {
            const int nbuf = (kt + 1) & 1;
            const float4* so4 = (const float4*)(Wo + (kt + 1) * 2048);
#pragma unroll
            for (int p = 0; p < 2; p++)
                cp16(&((float4*)wsm[nbuf])[t + p * 256], so4 + t + p * 256);
            cp_commit();
            cp_wait<1>();
        } else {
            cp_wait<0>();
        }
        __syncthreads();
        const int b = kt & 1;
#pragma unroll
        for (int ii = 0; ii < 16; ii++) {
            const int i = kt * 16 + ii;
            const float wv = wsm[b][ii * 128 + tc];
            const u64 w2 = pack2(wv, wv);
            const ulonglong2 cc = ((const ulonglong2*)a_t[i])[grp];
            acc[0] = fma2(w2, cc.x, acc[0]);
            acc[1] = fma2(w2, cc.y, acc[1]);
        }
        __syncthreads();
    }

    float val[4];
    unpack2(acc[0], val[0], val[1]);
    unpack2(acc[1], val[2], val[3]);
#pragma unroll
    for (int jj = 0; jj < 4; jj++) {
        const int j = grp * 4 + jj;
        val[jj] += s[(nb + j) * NS + tc];
        vals[j][tc] = val[jj];
    }
    __syncthreads();

    // warp w reduces node w (8 warps, 8 nodes)
    {
        float sv = 0.f, sq = 0.f;
#pragma unroll
        for (int c = 0; c < 4; c++) {
            const float x = vals[w][lane + 32 * c];
            sv += x;
            sq = fmaf(x, x, sq);
        }
#pragma unroll
        for (int off = 16; off > 0; off >>= 1) {
            sv += __shfl_xor_sync(0xffffffffu, sv, off);
            sq += __shfl_xor_sync(0xffffffffu, sq, off);
        }
        if (lane == 0) {
            const float mu = sv * (1.f / 128.f);
            mus[w] = mu;
            ivs[w] = rsqrtf(sq * (1.f / 128.f) - mu * mu + 1e-5f);
        }
    }
    __syncthreads();

    const float gm = gamma[tc], bt = beta[tc];
#pragma unroll
    for (int jj = 0; jj < 4; jj++) {
        const int j = grp * 4 + jj;
        out[(nb + j) * NS + tc] = (val[jj] - mus[j]) * ivs[j] * gm + bt;
    }
}

// ---------------------------------------------------------------------------
extern "C" void kernel_launch(void* const* d_in, const int* in_sizes, int n_in,
                              void* d_out, int out_size) {
    const float* s     = (const float*)d_in[0];
    const float* v     = (const float*)d_in[1];
    const float* Wq    = (const float*)d_in[2];
    const float* bq    = (const float*)d_in[3];
    const float* Wk    = (const float*)d_in[4];
    const float* bk    = (const float*)d_in[5];
    const float* Wv    = (const float*)d_in[6];
    const float* bv    = (const float*)d_in[7];
    const float* Wo    = (const float*)d_in[8];
    const float* bo    = (const float*)d_in[9];
    const float* gamma = (const float*)d_in[10];
    const float* beta  = (const float*)d_in[11];
    float* out = (float*)d_out;

    proj_kernel<<<N_NODES / PNODES, 256>>>(s, v, Wq, bq, Wk, bk, Wv, bv);
    attn_kernel<<<dim3(N_NODES / 64, H), 256>>>();
    out_kernel<<<N_NODES / ONODES, 256>>>(s, v, Wo, bo, gamma, beta, out);
}

// round 9
// speedup vs baseline: 1.1943x; 1.1943x over previous
#include <cuda_runtime.h>
#include <cuda_fp16.h>
#include <cstdint>

#define N_NODES 4096
#define NS 128
#define NV 16
#define H 8
#define D 16
#define COMB 144
#define HD 128   // H*D

typedef unsigned long long u64;

// ---- packed f32x2 helpers ----
__device__ __forceinline__ u64 pack2(float lo, float hi) {
    u64 d; asm("mov.b64 %0, {%1, %2};" : "=l"(d) : "f"(lo), "f"(hi)); return d;
}
__device__ __forceinline__ void unpack2(u64 x, float& lo, float& hi) {
    asm("mov.b64 {%0, %1}, %2;" : "=f"(lo), "=f"(hi) : "l"(x));
}
__device__ __forceinline__ u64 fma2(u64 a, u64 b, u64 c) {
    u64 d; asm("fma.rn.f32x2 %0, %1, %2, %3;" : "=l"(d) : "l"(a), "l"(b), "l"(c)); return d;
}
// ---- f16 mma, fp32 accumulate (PV) ----
__device__ __forceinline__ void mma_f16(float* d, const uint32_t* a, uint32_t b0, uint32_t b1) {
    asm("mma.sync.aligned.m16n8k16.row.col.f32.f16.f16.f32 "
        "{%0,%1,%2,%3},{%4,%5,%6,%7},{%8,%9},{%0,%1,%2,%3};"
        : "+f"(d[0]), "+f"(d[1]), "+f"(d[2]), "+f"(d[3])
        : "r"(a[0]), "r"(a[1]), "r"(a[2]), "r"(a[3]), "r"(b0), "r"(b1));
}
// ---- f16 mma, f16 accumulate (S scores; D packed f16x2 = exp input) ----
__device__ __forceinline__ void mma_f16_s(uint32_t& d0, uint32_t& d1, const uint32_t* a,
                                          uint32_t b0, uint32_t b1) {
    asm("mma.sync.aligned.m16n8k16.row.col.f16.f16.f16.f16 "
        "{%0,%1},{%2,%3,%4,%5},{%6,%7},{%8,%9};"
        : "=r"(d0), "=r"(d1)
        : "r"(a[0]), "r"(a[1]), "r"(a[2]), "r"(a[3]), "r"(b0), "r"(b1),
          "r"(0u), "r"(0u));
}
__device__ __forceinline__ uint32_t h2bits(__half2 h) {
    return *reinterpret_cast<uint32_t*>(&h);
}
__device__ __forceinline__ __half2 bits2h(uint32_t u) {
    return *reinterpret_cast<__half2*>(&u);
}
// ---- cp.async helpers ----
__device__ __forceinline__ uint32_t smem_u32(const void* p) {
    uint32_t a;
    asm("{ .reg .u64 t; cvta.to.shared.u64 t, %1; cvt.u32.u64 %0, t; }" : "=r"(a) : "l"(p));
    return a;
}
__device__ __forceinline__ void cp16(uint32_t smem_dst, const void* gsrc) {
    asm volatile("cp.async.cg.shared.global [%0], [%1], 16;" :: "r"(smem_dst), "l"(gsrc));
}
__device__ __forceinline__ void cp_commit() { asm volatile("cp.async.commit_group;"); }
template <int N>
__device__ __forceinline__ void cp_wait() {
    asm volatile("cp.async.wait_group %0;" :: "n"(N) : "memory");
}
__device__ __forceinline__ void barx(int id) {   // 128-thread named barrier
    asm volatile("bar.sync %0, 128;" :: "r"(id) : "memory");
}

// Scratch (static device globals — no allocation allowed)
__device__ __half g_qh[N_NODES * HD];   // q * (D^-0.5 * log2e), f16, [node][ch]
__device__ __half g_kh[N_NODES * HD];   // k, f16, [node][ch]
__device__ __half g_vth[HD * N_NODES];  // v, f16, TRANSPOSED [ch][node]
__device__ float  g_attn[N_NODES * HD];

// ---------------------------------------------------------------------------
// Kernel 1: projections (R6 measured-best: 128 threads, 8 nodes/block,
// cp.async double-buffered weight tiles).
// ---------------------------------------------------------------------------
#define PNODES 8
__global__ void proj_kernel(const float* __restrict__ s, const float* __restrict__ v,
                            const float* __restrict__ Wq, const float* __restrict__ bq,
                            const float* __restrict__ Wk, const float* __restrict__ bk,
                            const float* __restrict__ Wv, const float* __restrict__ bv) {
    const int nb = blockIdx.x * PNODES;
    const int t = threadIdx.x;
    __shared__ __align__(16) float comb_t[COMB][PNODES];
    __shared__ __align__(16) float wsm[2][2][16 * 128];

    for (int idx = t; idx < COMB * PNODES; idx += 128) {
        const int j = idx & 7;
        const int i = idx >> 3;
        float val;
        if (i < NS) {
            val = s[(nb + j) * NS + i];
        } else {
            const int vi = i - NS;
            const float* vp = &v[(nb + j) * NV * 3 + vi * 3];
            float x = vp[0], y = vp[1], z = vp[2];
            val = sqrtf(fmaxf(x * x + y * y + z * z, 1e-8f));
        }
        comb_t[i][j] = val;
    }

    const float bqv = bq[t], bkv = bk[t], bvv = bv[t];
    u64 aq[4], ak[4], av[4];
#pragma unroll
    for (int jj = 0; jj < 4; jj++) {
        aq[jj] = pack2(bqv, bqv);
        ak[jj] = pack2(bkv, bkv);
        av[jj] = pack2(bvv, bvv);
    }

    {   // Phase A: Wq + Wk over COMB=144 (9 tiles), double-buffered
        const uint32_t b00 = smem_u32(wsm[0][0]);
        const uint32_t b01 = smem_u32(wsm[0][1]);
#pragma unroll
        for (int p = 0; p < 4; p++) {
            cp16(b00 + (t + p * 128) * 16, (const float4*)Wq + t + p * 128);
            cp16(b01 + (t + p * 128) * 16, (const float4*)Wk + t + p * 128);
        }
        cp_commit();
        for (int kt = 0; kt < 9; kt++) {
            if (kt < 8) {
                const int nbuf = (kt + 1) & 1;
                const uint32_t d0 = smem_u32(wsm[nbuf][0]);
                const uint32_t d1 = smem_u32(wsm[nbuf][1]);
                const float4* sq4 = (const float4*)(Wq + (kt + 1) * 2048);
                const float4* sk4 = (const float4*)(Wk + (kt + 1) * 2048);
#pragma unroll
                for (int p = 0; p < 4; p++) {
                    cp16(d0 + (t + p * 128) * 16, sq4 + t + p * 128);
                    cp16(d1 + (t + p * 128) * 16, sk4 + t + p * 128);
                }
                cp_commit();
                cp_wait<1>();
            } else {
                cp_wait<0>();
            }
            __syncthreads();
            const int b = kt & 1;
#pragma unroll
            for (int ii = 0; ii < 16; ii++) {
                const int i = kt * 16 + ii;
                const float wq = wsm[b][0][ii * 128 + t];
                const float wk = wsm[b][1][ii * 128 + t];
                const u64 wq2 = pack2(wq, wq);
                const u64 wk2 = pack2(wk, wk);
                const ulonglong2* cr = (const ulonglong2*)comb_t[i];
                const ulonglong2 ca = cr[0], cb = cr[1];
                aq[0] = fma2(wq2, ca.x, aq[0]); aq[1] = fma2(wq2, ca.y, aq[1]);
                aq[2] = fma2(wq2, cb.x, aq[2]); aq[3] = fma2(wq2, cb.y, aq[3]);
                ak[0] = fma2(wk2, ca.x, ak[0]); ak[1] = fma2(wk2, ca.y, ak[1]);
                ak[2] = fma2(wk2, cb.x, ak[2]); ak[3] = fma2(wk2, cb.y, ak[3]);
            }
            __syncthreads();
        }
    }
    {   // Phase B: Wv over NS=128 (8 tiles)
        const uint32_t b00 = smem_u32(wsm[0][0]);
#pragma unroll
        for (int p = 0; p < 4; p++)
            cp16(b00 + (t + p * 128) * 16, (const float4*)Wv + t + p * 128);
        cp_commit();
        for (int kt = 0; kt < 8; kt++) {
            if (kt < 7) {
                const int nbuf = (kt + 1) & 1;
                const uint32_t d0 = smem_u32(wsm[nbuf][0]);
                const float4* sv4 = (const float4*)(Wv + (kt + 1) * 2048);
#pragma unroll
                for (int p = 0; p < 4; p++)
                    cp16(d0 + (t + p * 128) * 16, sv4 + t + p * 128);
                cp_commit();
                cp_wait<1>();
            } else {
                cp_wait<0>();
            }
            __syncthreads();
            const int b = kt & 1;
#pragma unroll
            for (int ii = 0; ii < 16; ii++) {
                const int i = kt * 16 + ii;
                const float wv = wsm[b][0][ii * 128 + t];
                const u64 wv2 = pack2(wv, wv);
                const ulonglong2* cr = (const ulonglong2*)comb_t[i];
                const ulonglong2 ca = cr[0], cb = cr[1];
                av[0] = fma2(wv2, ca.x, av[0]); av[1] = fma2(wv2, ca.y, av[1]);
                av[2] = fma2(wv2, cb.x, av[2]); av[3] = fma2(wv2, cb.y, av[3]);
            }
            __syncthreads();
        }
    }

    const float CS = 0.25f * 1.4426950408889634f;  // D^-0.5 * log2(e), folded into q
#pragma unroll
    for (int jj = 0; jj < 4; jj++) {
        float lo, hi;
        unpack2(aq[jj], lo, hi);
        g_qh[(nb + 2 * jj) * HD + t]     = __float2half(lo * CS);
        g_qh[(nb + 2 * jj + 1) * HD + t] = __float2half(hi * CS);
        unpack2(ak[jj], lo, hi);
        g_kh[(nb + 2 * jj) * HD + t]     = __float2half(lo);
        g_kh[(nb + 2 * jj + 1) * HD + t] = __float2half(hi);
        unpack2(av[jj], lo, hi);
        g_vth[t * N_NODES + (nb + 2 * jj)]     = __float2half(lo);
        g_vth[t * N_NODES + (nb + 2 * jj + 1)] = __float2half(hi);
    }
}

// ---------------------------------------------------------------------------
// Kernel 2: f16 mma flash attention, 8 warps, in-block split-K (R6) PLUS
// cp.async DOUBLE-BUFFERED K/V tiles: tile i+1 streams into the alternate
// buffer while tile i computes, removing the exposed LDG latency that R6/R7
// evidence shows is the actual binder (~70us invariant under warp x2 and
// MMA-count x0.8).
// Inner loop = R7: f16-acc S-mma (output = exp input, no cvt), HADD2 row
// sums flushed to fp32 per tile (no ones-MMA).
// ---------------------------------------------------------------------------
__global__ void attn_kernel() {
    const int h = blockIdx.y;
    const int qbase = blockIdx.x * 64;
    const int gid = threadIdx.x >> 7;   // key-split group 0/1
    const int tl = threadIdx.x & 127;
    const int w = tl >> 5;
    const int lane = tl & 31;
    const int g = lane >> 2;
    const int tid = lane & 3;

    // [group][buffer] private double-buffered tiles
    __shared__ __align__(16) uint32_t Ksw[2][2][128 * 12];
    __shared__ __align__(16) uint32_t Vsw[2][2][16 * 68];
    __shared__ float mrg[128][10];

    uint32_t qa[4];
    {
        const __half* Q0 = g_qh + (qbase + w * 16 + g) * HD + h * D;
        const __half* Q1 = Q0 + 8 * HD;
        qa[0] = *(const uint32_t*)(Q0 + 2 * tid);
        qa[1] = *(const uint32_t*)(Q1 + 2 * tid);
        qa[2] = *(const uint32_t*)(Q0 + 2 * tid + 8);
        qa[3] = *(const uint32_t*)(Q1 + 2 * tid + 8);
    }

    float o0[4] = {0.f, 0.f, 0.f, 0.f};
    float o1[4] = {0.f, 0.f, 0.f, 0.f};
    float l0 = 0.f, l1 = 0.f;

    const int vrow = tl & 15;
    const int vchunk = tl >> 4;
    const uint32_t kbase0 = smem_u32(Ksw[gid][0]);
    const uint32_t kbase1 = smem_u32(Ksw[gid][1]);
    const uint32_t vbase0 = smem_u32(Vsw[gid][0]);
    const uint32_t vbase1 = smem_u32(Vsw[gid][1]);
    const uint32_t kdst0 = kbase0 + tl * 48;                      // tl*12 words
    const uint32_t kdst1 = kbase1 + tl * 48;
    const uint32_t vdst0 = vbase0 + (vrow * 68 + vchunk * 8) * 4;
    const uint32_t vdst1 = vbase1 + (vrow * 68 + vchunk * 8) * 4;

    // preload tile 0 of this group into buffer 0
    {
        const int kt = gid * 128;
        const __half* kp = g_kh + (kt + tl) * HD + h * D;
        cp16(kdst0, kp);
        cp16(kdst0 + 16, kp + 8);
        const __half* vp = g_vth + (h * D + vrow) * N_NODES + kt + vchunk * 16;
        cp16(vdst0, vp);
        cp16(vdst0 + 16, vp + 8);
        cp_commit();
    }

    for (int i = 0; i < 16; i++) {
        const int b = i & 1;
        if (i < 15) {
            // stream tile i+1 into the alternate buffer
            const int kt = (2 * (i + 1) + gid) * 128;
            const uint32_t kd = b ? kdst0 : kdst1;   // buffer (i+1)&1
            const uint32_t vd = b ? vdst0 : vdst1;
            const __half* kp = g_kh + (kt + tl) * HD + h * D;
            cp16(kd, kp);
            cp16(kd + 16, kp + 8);
            const __half* vp = g_vth + (h * D + vrow) * N_NODES + kt + vchunk * 16;
            cp16(vd, vp);
            cp16(vd + 16, vp + 8);
            cp_commit();
            cp_wait<1>();   // oldest group (tile i) complete
        } else {
            cp_wait<0>();
        }
        barx(1 + gid);      // tile i visible to all warps in this group

        const uint32_t* Kg = Ksw[gid][b];
        const uint32_t* Vg = Vsw[gid][b];
        __half2 lh0 = __half2half2(__float2half(0.f));
        __half2 lh1 = lh0;
#pragma unroll
        for (int u = 0; u < 8; u++) {       // 16 keys
            uint32_t sA0, sA1, sB0, sB1;
            const int kA = (16 * u + g) * 12;
            const int kB = (16 * u + 8 + g) * 12;
            mma_f16_s(sA0, sA1, qa, Kg[kA + tid], Kg[kA + 4 + tid]);
            mma_f16_s(sB0, sB1, qa, Kg[kB + tid], Kg[kB + 4 + tid]);
            const __half2 e0 = h2exp2(bits2h(sA0));
            const __half2 e1 = h2exp2(bits2h(sA1));
            const __half2 e2 = h2exp2(bits2h(sB0));
            const __half2 e3 = h2exp2(bits2h(sB1));
            lh0 = __hadd2(lh0, __hadd2(e0, e2));
            lh1 = __hadd2(lh1, __hadd2(e1, e3));
            uint32_t pa[4];
            pa[0] = h2bits(e0);
            pa[1] = h2bits(e1);
            pa[2] = h2bits(e2);
            pa[3] = h2bits(e3);
            const int vb = 8 * u + tid;
            mma_f16(o0, pa, Vg[g * 68 + vb],       Vg[g * 68 + 4 + vb]);
            mma_f16(o1, pa, Vg[(g + 8) * 68 + vb], Vg[(g + 8) * 68 + 4 + vb]);
        }
        const float2 f0 = __half22float2(lh0);
        const float2 f1 = __half22float2(lh1);
        l0 += f0.x + f0.y;
        l1 += f1.x + f1.y;

        barx(1 + gid);      // all warps done reading buf b before it's refilled
    }

    // quad-reduce row sums
    l0 += __shfl_xor_sync(0xffffffffu, l0, 1);
    l0 += __shfl_xor_sync(0xffffffffu, l0, 2);
    l1 += __shfl_xor_sync(0xffffffffu, l1, 1);
    l1 += __shfl_xor_sync(0xffffffffu, l1, 2);

    // merge split-K partials (fp32) through smem
    if (gid == 1) {
        float* m = mrg[tl];
        m[0] = o0[0]; m[1] = o0[1]; m[2] = o0[2]; m[3] = o0[3];
        m[4] = o1[0]; m[5] = o1[1]; m[6] = o1[2]; m[7] = o1[3];
        m[8] = l0; m[9] = l1;
    }
    __syncthreads();
    if (gid == 0) {
        const float* m = mrg[tl];
        const float i0 = 1.f / (l0 + m[8]);
        const float i1 = 1.f / (l1 + m[9]);
        float* O0 = &g_attn[(qbase + w * 16 + g) * HD + h * D];
        float* O1 = O0 + 8 * HD;
        *(float2*)&O0[2 * tid]     = make_float2((o0[0] + m[0]) * i0, (o0[1] + m[1]) * i0);
        *(float2*)&O1[2 * tid]     = make_float2((o0[2] + m[2]) * i1, (o0[3] + m[3]) * i1);
        *(float2*)&O0[2 * tid + 8] = make_float2((o1[0] + m[4]) * i0, (o1[1] + m[5]) * i0);
        *(float2*)&O1[2 * tid + 8] = make_float2((o1[2] + m[6]) * i1, (o1[3] + m[7]) * i1);
    }
}

// ---------------------------------------------------------------------------
// Kernel 3: out proj + residual + LayerNorm (R6 structure, 128 threads)
// + v passthrough folded in (deletes the memcpy launch).
// ---------------------------------------------------------------------------
#define ONODES 8
__global__ void out_kernel(const float* __restrict__ s, const float* __restrict__ vin,
                           const float* __restrict__ Wo, const float* __restrict__ bo,
                           const float* __restrict__ gamma, const float* __restrict__ beta,
                           float* __restrict__ out) {
    const int nb = blockIdx.x * ONODES;
    const int t = threadIdx.x;
    const int w = t >> 5;
    const int lane = t & 31;
    __shared__ __align__(16) float a_t[HD][ONODES];
    __shared__ __align__(16) float wsm[2][16 * 128];
    __shared__ float vals[ONODES][128];
    __shared__ float mus[ONODES], ivs[ONODES];

    // v passthrough: 96 float4 per block
    {
        const float4* vsrc = (const float4*)vin + blockIdx.x * 96;
        float4* vdst = (float4*)(out + N_NODES * NS) + blockIdx.x * 96;
        if (t < 96) vdst[t] = vsrc[t];
    }

    for (int idx = t; idx < HD * ONODES; idx += 128) {
        const int j = idx & 7;
        const int i = idx >> 3;
        a_t[i][j] = g_attn[(nb + j) * HD + i];
    }

    const float bov = bo[t];
    u64 acc[4];
#pragma unroll
    for (int jj = 0; jj < 4; jj++) acc[jj] = pack2(bov, bov);

    {
        const uint32_t b0a = smem_u32(wsm[0]);
#pragma unroll
        for (int p = 0; p < 4; p++)
            cp16(b0a + (t + p * 128) * 16, (const float4*)Wo + t + p * 128);
        cp_commit();
    }
    for (int kt = 0; kt < 8; kt++) {
        if (kt < 7) {
            const int nbuf = (kt + 1) & 1;
            const uint32_t d0 = smem_u32(wsm[nbuf]);
            const float4* so4 = (const float4*)(Wo + (kt + 1) * 2048);
#pragma unroll
            for (int p = 0; p < 4; p++)
                cp16(d0 + (t + p * 128) * 16, so4 + t + p * 128);
            cp_commit();
            cp_wait<1>();
        } else {
            cp_wait<0>();
        }
        __syncthreads();
        const int b = kt & 1;
#pragma unroll
        for (int ii = 0; ii < 16; ii++) {
            const int i = kt * 16 + ii;
            const float wv = wsm[b][ii * 128 + t];
            const u64 w2 = pack2(wv, wv);
            const ulonglong2* cr = (const ulonglong2*)a_t[i];
            const ulonglong2 ca = cr[0], cb = cr[1];
            acc[0] = fma2(w2, ca.x, acc[0]); acc[1] = fma2(w2, ca.y, acc[1]);
            acc[2] = fma2(w2, cb.x, acc[2]); acc[3] = fma2(w2, cb.y, acc[3]);
        }
        __syncthreads();
    }

    float val[8];
#pragma unroll
    for (int jj = 0; jj < 4; jj++) unpack2(acc[jj], val[2 * jj], val[2 * jj + 1]);
#pragma unroll
    for (int j = 0; j < 8; j++) {
        val[j] += s[(nb + j) * NS + t];
        vals[j][t] = val[j];
    }
    __syncthreads();

#pragma unroll
    for (int jj = 0; jj < 2; jj++) {
        const int j = w * 2 + jj;
        float sv = 0.f, sq = 0.f;
#pragma unroll
        for (int c = 0; c < 4; c++) {
            const float x = vals[j][lane + 32 * c];
            sv += x;
            sq = fmaf(x, x, sq);
        }
#pragma unroll
        for (int off = 16; off > 0; off >>= 1) {
            sv += __shfl_xor_sync(0xffffffffu, sv, off);
            sq += __shfl_xor_sync(0xffffffffu, sq, off);
        }
        if (lane == 0) {
            const float mu = sv * (1.f / 128.f);
            mus[j] = mu;
            ivs[j] = rsqrtf(sq * (1.f / 128.f) - mu * mu + 1e-5f);
        }
    }
    __syncthreads();

    const float gm = gamma[t], bt = beta[t];
#pragma unroll
    for (int j = 0; j < 8; j++) {
        out[(nb + j) * NS + t] = (val[j] - mus[j]) * ivs[j] * gm + bt;
    }
}

// ---------------------------------------------------------------------------
extern "C" void kernel_launch(void* const* d_in, const int* in_sizes, int n_in,
                              void* d_out, int out_size) {
    const float* s     = (const float*)d_in[0];
    const float* v     = (const float*)d_in[1];
    const float* Wq    = (const float*)d_in[2];
    const float* bq    = (const float*)d_in[3];
    const float* Wk    = (const float*)d_in[4];
    const float* bk    = (const float*)d_in[5];
    const float* Wv    = (const float*)d_in[6];
    const float* bv    = (const float*)d_in[7];
    const float* Wo    = (const float*)d_in[8];
    const float* bo    = (const float*)d_in[9];
    const float* gamma = (const float*)d_in[10];
    const float* beta  = (const float*)d_in[11];
    float* out = (float*)d_out;

    proj_kernel<<<N_NODES / PNODES, 128>>>(s, v, Wq, bq, Wk, bk, Wv, bv);
    attn_kernel<<<dim3(N_NODES / 64, H), 256>>>();
    out_kernel<<<N_NODES / ONODES, 128>>>(s, v, Wo, bo, gamma, beta, out);
}

// round 11
// speedup vs baseline: 1.3624x; 1.1407x over previous
#include <cuda_runtime.h>
#include <cuda_fp16.h>
#include <cstdint>

#define N_NODES 4096
#define NS 128
#define NV 16
#define H 8
#define D 16
#define COMB 144
#define HD 128   // H*D

typedef unsigned long long u64;

// ---- packed f32x2 helpers (out_kernel GEMV) ----
__device__ __forceinline__ u64 pack2(float lo, float hi) {
    u64 d; asm("mov.b64 %0, {%1, %2};" : "=l"(d) : "f"(lo), "f"(hi)); return d;
}
__device__ __forceinline__ void unpack2(u64 x, float& lo, float& hi) {
    asm("mov.b64 {%0, %1}, %2;" : "=f"(lo), "=f"(hi) : "l"(x));
}
__device__ __forceinline__ u64 fma2(u64 a, u64 b, u64 c) {
    u64 d; asm("fma.rn.f32x2 %0, %1, %2, %3;" : "=l"(d) : "l"(a), "l"(b), "l"(c)); return d;
}
// ---- f16 mma, fp32 accumulate ----
__device__ __forceinline__ void mma_f16(float* d, const uint32_t* a, uint32_t b0, uint32_t b1) {
    asm("mma.sync.aligned.m16n8k16.row.col.f32.f16.f16.f32 "
        "{%0,%1,%2,%3},{%4,%5,%6,%7},{%8,%9},{%0,%1,%2,%3};"
        : "+f"(d[0]), "+f"(d[1]), "+f"(d[2]), "+f"(d[3])
        : "r"(a[0]), "r"(a[1]), "r"(a[2]), "r"(a[3]), "r"(b0), "r"(b1));
}
// ---- f16 mma, f16 accumulate (attn scores) ----
__device__ __forceinline__ void mma_f16_s(uint32_t& d0, uint32_t& d1, const uint32_t* a,
                                          uint32_t b0, uint32_t b1) {
    asm("mma.sync.aligned.m16n8k16.row.col.f16.f16.f16.f16 "
        "{%0,%1},{%2,%3,%4,%5},{%6,%7},{%8,%9};"
        : "=r"(d0), "=r"(d1)
        : "r"(a[0]), "r"(a[1]), "r"(a[2]), "r"(a[3]), "r"(b0), "r"(b1),
          "r"(0u), "r"(0u));
}
__device__ __forceinline__ uint32_t h2bits(__half2 h) {
    return *reinterpret_cast<uint32_t*>(&h);
}
__device__ __forceinline__ __half2 bits2h(uint32_t u) {
    return *reinterpret_cast<__half2*>(&u);
}
// ---- cp.async ----
__device__ __forceinline__ uint32_t smem_u32(const void* p) {
    uint32_t a;
    asm("{ .reg .u64 t; cvta.to.shared.u64 t, %1; cvt.u32.u64 %0, t; }" : "=r"(a) : "l"(p));
    return a;
}
__device__ __forceinline__ void cp16(uint32_t smem_dst, const void* gsrc) {
    asm volatile("cp.async.cg.shared.global [%0], [%1], 16;" :: "r"(smem_dst), "l"(gsrc));
}
__device__ __forceinline__ void cp_commit() { asm volatile("cp.async.commit_group;"); }
template <int N>
__device__ __forceinline__ void cp_wait() {
    asm volatile("cp.async.wait_group %0;" :: "n"(N) : "memory");
}
__device__ __forceinline__ void barx(int id) {
    asm volatile("bar.sync %0, 128;" :: "r"(id) : "memory");
}

// Scratch (static device globals)
__device__ __half g_qh[N_NODES * HD];     // q * (D^-0.5 * log2e)
__device__ __half g_kh[N_NODES * HD];
__device__ __half g_vth[HD * N_NODES];    // v TRANSPOSED [ch][node]
__device__ float  g_attn[N_NODES * HD];
__device__ __half g_Wqk_t[256 * COMB];    // TRANSPOSED [n=q0..127|k0..127][k=144]
__device__ __half g_Wv_t[HD * NS];        // TRANSPOSED [n=128][k=128]

// ---------------------------------------------------------------------------
// Kernel 0: one-off f32 -> f16 TRANSPOSED weight conversion.
// block = output column n (256), thread = input dim k (144).
// ---------------------------------------------------------------------------
__global__ void convw_kernel(const float* __restrict__ Wq, const float* __restrict__ Wk,
                             const float* __restrict__ Wv) {
    const int n = blockIdx.x;     // 0..255
    const int k = threadIdx.x;    // 0..143
    const float w = (n < 128) ? Wq[k * 128 + n] : Wk[k * 128 + (n - 128)];
    g_Wqk_t[n * COMB + k] = __float2half(w);
    if (n < 128 && k < 128) g_Wv_t[n * NS + k] = __float2half(Wv[k * 128 + n]);
}

// ---------------------------------------------------------------------------
// Kernel 1: tensor-core projections. Block = 32 nodes, 256 threads (8 warps).
// mw = w>>2 picks 16-node m-tile; nw = w&3 picks 64-col n-slice.
// ALL fragments via direct 32-bit smem reads using the attn kernel's proven
// patterns (A: rows g/g+8 x words tid/tid+4; B: n-row g x words tid/tid+4
// from [n][k]-transposed weights). No ldmatrix.
// Bank math (mod 32): comb words 84g+tid -> bases {0,4,..,28}+tid = 32
// distinct; weight words 12g+tid -> bases {0,12,24,4,16,28,8,20}+tid = 32
// distinct. Conflict-free.
// ---------------------------------------------------------------------------
#define SA 168    // comb stride in halves (84 words)
#define SWT 12    // weight-tile stride in words per n-row (8 used + 4 pad)
#define SV 138
__global__ __launch_bounds__(256) void proj_kernel(
        const float* __restrict__ s, const float* __restrict__ v,
        const float* __restrict__ bq, const float* __restrict__ bk,
        const float* __restrict__ bv) {
    const int nb = blockIdx.x * 32;
    const int t = threadIdx.x;
    const int w = t >> 5, lane = t & 31;
    const int mw = w >> 2, nw = w & 3;
    const int g = lane >> 2, tid = lane & 3;
    const int m0 = mw * 16;

    __shared__ __align__(16) __half comb[32 * SA];        // 10.5 KB
    __shared__ __align__(16) uint32_t wtb[2][256 * SWT];  // 24 KB
    __shared__ __align__(16) __half vsm[32 * SV];         // 8.6 KB

    // build comb f16: s rows + vnorm
    for (int i = t; i < 32 * 32; i += 256) {
        const int node = i >> 5, c4 = i & 31;
        const float4 s4 = ((const float4*)(s + (nb + node) * NS))[c4];
        __half2* dst = (__half2*)(comb + node * SA + c4 * 4);
        dst[0] = __floats2half2_rn(s4.x, s4.y);
        dst[1] = __floats2half2_rn(s4.z, s4.w);
    }
    for (int i = t; i < 32 * NV; i += 256) {
        const int node = i >> 4, vi = i & 15;
        const float* vp = v + (nb + node) * NV * 3 + vi * 3;
        const float x = vp[0], y = vp[1], z = vp[2];
        comb[node * SA + 128 + vi] = __float2half(sqrtf(fmaxf(x * x + y * y + z * z, 1e-8f)));
    }

    const uint32_t* cw = (const uint32_t*)comb;
    const uint32_t wb[2] = { smem_u32(wtb[0]), smem_u32(wtb[1]) };

    // ---- qk GEMM: [32 x 144] @ Wqk_t^T -> [32 x 256], 9 k-steps ----
    float cq[8][4];
#pragma unroll
    for (int i = 0; i < 8; i++)
#pragma unroll
        for (int j = 0; j < 4; j++) cq[i][j] = 0.f;

    {   // stage k-step 0: 256 n-rows x 32B (2 chunks each)
#pragma unroll
        for (int p = 0; p < 2; p++) {
            const int cid = t + p * 256;
            const int r = cid >> 1, hf = cid & 1;
            cp16(wb[0] + r * 48 + hf * 16,
                 (const char*)g_Wqk_t + r * (COMB * 2) + hf * 16);
        }
        cp_commit();
    }
    __syncthreads();   // comb ready + ordering

    for (int ks = 0; ks < 9; ks++) {
        if (ks < 8) {
            const uint32_t dst = wb[(ks + 1) & 1];
#pragma unroll
            for (int p = 0; p < 2; p++) {
                const int cid = t + p * 256;
                const int r = cid >> 1, hf = cid & 1;
                cp16(dst + r * 48 + hf * 16,
                     (const char*)g_Wqk_t + r * (COMB * 2) + (ks + 1) * 32 + hf * 16);
            }
            cp_commit();
            cp_wait<1>();
        } else {
            cp_wait<0>();
        }
        __syncthreads();
        const uint32_t* wt = wtb[ks & 1];

        uint32_t a[4];
        a[0] = cw[(m0 + g) * 84 + ks * 8 + tid];
        a[1] = cw[(m0 + g + 8) * 84 + ks * 8 + tid];
        a[2] = cw[(m0 + g) * 84 + ks * 8 + 4 + tid];
        a[3] = cw[(m0 + g + 8) * 84 + ks * 8 + 4 + tid];
#pragma unroll
        for (int bt = 0; bt < 8; bt++) {
            const uint32_t* br = wt + (nw * 64 + bt * 8 + g) * SWT;
            mma_f16(cq[bt], a, br[tid], br[4 + tid]);
        }
        __syncthreads();
    }

    // qk epilogue: bias (exact f32), scale q, store f16
    {
        const float* barr = (nw < 2) ? bq : bk;
        const float scale = (nw < 2) ? 0.25f * 1.4426950408889634f : 1.0f;
        __half* dst = (nw < 2) ? g_qh : g_kh;
#pragma unroll
        for (int bt = 0; bt < 8; bt++) {
            const int c = nw * 64 + bt * 8 + 2 * tid;
            const int cl = c & 127;
            const float b0 = barr[cl], b1 = barr[cl + 1];
            const int r0 = nb + m0 + g;
            *(__half2*)(dst + r0 * HD + cl) =
                __floats2half2_rn((cq[bt][0] + b0) * scale, (cq[bt][1] + b1) * scale);
            *(__half2*)(dst + (r0 + 8) * HD + cl) =
                __floats2half2_rn((cq[bt][2] + b0) * scale, (cq[bt][3] + b1) * scale);
        }
    }

    // ---- v GEMM: [32 x 128] @ Wv_t^T -> [32 x 128], 8 k-steps ----
    float cv[4][4];
#pragma unroll
    for (int i = 0; i < 4; i++)
#pragma unroll
        for (int j = 0; j < 4; j++) cv[i][j] = 0.f;

    {   // stage k-step 0: 128 n-rows x 32B
        const int r = t >> 1, hf = t & 1;
        cp16(wb[0] + r * 48 + hf * 16,
             (const char*)g_Wv_t + r * (NS * 2) + hf * 16);
        cp_commit();
    }
    for (int ks = 0; ks < 8; ks++) {
        if (ks < 7) {
            const uint32_t dst = wb[(ks + 1) & 1];
            const int r = t >> 1, hf = t & 1;
            cp16(dst + r * 48 + hf * 16,
                 (const char*)g_Wv_t + r * (NS * 2) + (ks + 1) * 32 + hf * 16);
            cp_commit();
            cp_wait<1>();
        } else {
            cp_wait<0>();
        }
        __syncthreads();
        const uint32_t* wt = wtb[ks & 1];

        uint32_t a[4];
        a[0] = cw[(m0 + g) * 84 + ks * 8 + tid];
        a[1] = cw[(m0 + g + 8) * 84 + ks * 8 + tid];
        a[2] = cw[(m0 + g) * 84 + ks * 8 + 4 + tid];
        a[3] = cw[(m0 + g + 8) * 84 + ks * 8 + 4 + tid];
#pragma unroll
        for (int bt = 0; bt < 4; bt++) {
            const uint32_t* br = wt + (nw * 32 + bt * 8 + g) * SWT;
            mma_f16(cv[bt], a, br[tid], br[4 + tid]);
        }
        __syncthreads();
    }

    // v epilogue: bias, f16 into vsm, then transpose to g_vth
#pragma unroll
    for (int bt = 0; bt < 4; bt++) {
        const int c = nw * 32 + bt * 8 + 2 * tid;
        const float b0 = bv[c], b1 = bv[c + 1];
        const int r0 = m0 + g;
        *(__half2*)(vsm + r0 * SV + c)       = __floats2half2_rn(cv[bt][0] + b0, cv[bt][1] + b1);
        *(__half2*)(vsm + (r0 + 8) * SV + c) = __floats2half2_rn(cv[bt][2] + b0, cv[bt][3] + b1);
    }
    __syncthreads();
    {
        const int d = t >> 1;
        const int npart = (t & 1) * 16;
#pragma unroll
        for (int i = 0; i < 8; i++) {
            const int node = npart + i * 2;
            __half2 p;
            p.x = vsm[node * SV + d];
            p.y = vsm[(node + 1) * SV + d];
            *(__half2*)(g_vth + d * N_NODES + nb + node) = p;
        }
    }
}

// ---------------------------------------------------------------------------
// Kernel 2: f16 mma flash attention (R9 champion, exact; typo-free store).
// ---------------------------------------------------------------------------
__global__ void attn_kernel() {
    const int h = blockIdx.y;
    const int qbase = blockIdx.x * 64;
    const int gid = threadIdx.x >> 7;
    const int tl = threadIdx.x & 127;
    const int w = tl >> 5;
    const int lane = tl & 31;
    const int g = lane >> 2;
    const int tid = lane & 3;

    __shared__ __align__(16) uint32_t Ksw[2][2][128 * 12];
    __shared__ __align__(16) uint32_t Vsw[2][2][16 * 68];
    __shared__ float mrg[128][10];

    uint32_t qa[4];
    {
        const __half* Q0 = g_qh + (qbase + w * 16 + g) * HD + h * D;
        const __half* Q1 = Q0 + 8 * HD;
        qa[0] = *(const uint32_t*)(Q0 + 2 * tid);
        qa[1] = *(const uint32_t*)(Q1 + 2 * tid);
        qa[2] = *(const uint32_t*)(Q0 + 2 * tid + 8);
        qa[3] = *(const uint32_t*)(Q1 + 2 * tid + 8);
    }

    float o0[4] = {0.f, 0.f, 0.f, 0.f};
    float o1[4] = {0.f, 0.f, 0.f, 0.f};
    float l0 = 0.f, l1 = 0.f;

    const int vrow = tl & 15;
    const int vchunk = tl >> 4;
    const uint32_t kdst0 = smem_u32(Ksw[gid][0]) + tl * 48;
    const uint32_t kdst1 = smem_u32(Ksw[gid][1]) + tl * 48;
    const uint32_t vdst0 = smem_u32(Vsw[gid][0]) + (vrow * 68 + vchunk * 8) * 4;
    const uint32_t vdst1 = smem_u32(Vsw[gid][1]) + (vrow * 68 + vchunk * 8) * 4;

    {
        const int kt = gid * 128;
        const __half* kp = g_kh + (kt + tl) * HD + h * D;
        cp16(kdst0, kp);
        cp16(kdst0 + 16, kp + 8);
        const __half* vp = g_vth + (h * D + vrow) * N_NODES + kt + vchunk * 16;
        cp16(vdst0, vp);
        cp16(vdst0 + 16, vp + 8);
        cp_commit();
    }

    for (int i = 0; i < 16; i++) {
        const int b = i & 1;
        if (i < 15) {
            const int kt = (2 * (i + 1) + gid) * 128;
            const uint32_t kd = b ? kdst0 : kdst1;
            const uint32_t vd = b ? vdst0 : vdst1;
            const __half* kp = g_kh + (kt + tl) * HD + h * D;
            cp16(kd, kp);
            cp16(kd + 16, kp + 8);
            const __half* vp = g_vth + (h * D + vrow) * N_NODES + kt + vchunk * 16;
            cp16(vd, vp);
            cp16(vd + 16, vp + 8);
            cp_commit();
            cp_wait<1>();
        } else {
            cp_wait<0>();
        }
        barx(1 + gid);

        const uint32_t* Kg = Ksw[gid][b];
        const uint32_t* Vg = Vsw[gid][b];
        __half2 lh0 = __half2half2(__float2half(0.f));
        __half2 lh1 = lh0;
#pragma unroll
        for (int u = 0; u < 8; u++) {
            uint32_t sA0, sA1, sB0, sB1;
            const int kA = (16 * u + g) * 12;
            const int kB = (16 * u + 8 + g) * 12;
            mma_f16_s(sA0, sA1, qa, Kg[kA + tid], Kg[kA + 4 + tid]);
            mma_f16_s(sB0, sB1, qa, Kg[kB + tid], Kg[kB + 4 + tid]);
            const __half2 e0 = h2exp2(bits2h(sA0));
            const __half2 e1 = h2exp2(bits2h(sA1));
            const __half2 e2 = h2exp2(bits2h(sB0));
            const __half2 e3 = h2exp2(bits2h(sB1));
            lh0 = __hadd2(lh0, __hadd2(e0, e2));
            lh1 = __hadd2(lh1, __hadd2(e1, e3));
            uint32_t pa[4];
            pa[0] = h2bits(e0);
            pa[1] = h2bits(e1);
            pa[2] = h2bits(e2);
            pa[3] = h2bits(e3);
            const int vb = 8 * u + tid;
            mma_f16(o0, pa, Vg[g * 68 + vb],       Vg[g * 68 + 4 + vb]);
            mma_f16(o1, pa, Vg[(g + 8) * 68 + vb], Vg[(g + 8) * 68 + 4 + vb]);
        }
        const float2 f0 = __half22float2(lh0);
        const float2 f1 = __half22float2(lh1);
        l0 += f0.x + f0.y;
        l1 += f1.x + f1.y;

        barx(1 + gid);
    }

    l0 += __shfl_xor_sync(0xffffffffu, l0, 1);
    l0 += __shfl_xor_sync(0xffffffffu, l0, 2);
    l1 += __shfl_xor_sync(0xffffffffu, l1, 1);
    l1 += __shfl_xor_sync(0xffffffffu, l1, 2);

    if (gid == 1) {
        float* m = mrg[tl];
        m[0] = o0[0]; m[1] = o0[1]; m[2] = o0[2]; m[3] = o0[3];
        m[4] = o1[0]; m[5] = o1[1]; m[6] = o1[2]; m[7] = o1[3];
        m[8] = l0; m[9] = l1;
    }
    __syncthreads();
    if (gid == 0) {
        const float* m = mrg[tl];
        const float i0 = 1.f / (l0 + m[8]);
        const float i1 = 1.f / (l1 + m[9]);
        float* O0 = &g_attn[(qbase + w * 16 + g) * HD + h * D];
        float* O1 = O0 + 8 * HD;
        *(float2*)&O0[2 * tid]     = make_float2((o0[0] + m[0]) * i0, (o0[1] + m[1]) * i0);
        *(float2*)&O1[2 * tid]     = make_float2((o0[2] + m[2]) * i1, (o0[3] + m[3]) * i1);
        *(float2*)&O0[2 * tid + 8] = make_float2((o1[0] + m[4]) * i0, (o1[1] + m[5]) * i0);
        *(float2*)&O1[2 * tid + 8] = make_float2((o1[2] + m[6]) * i1, (o1[3] + m[7]) * i1);
    }
}

// ---------------------------------------------------------------------------
// Kernel 3: out proj + residual + LayerNorm + v passthrough (R9, unchanged).
// ---------------------------------------------------------------------------
#define ONODES 8
__global__ void out_kernel(const float* __restrict__ s, const float* __restrict__ vin,
                           const float* __restrict__ Wo, const float* __restrict__ bo,
                           const float* __restrict__ gamma, const float* __restrict__ beta,
                           float* __restrict__ out) {
    const int nb = blockIdx.x * ONODES;
    const int t = threadIdx.x;
    const int w = t >> 5;
    const int lane = t & 31;
    __shared__ __align__(16) float a_t[HD][ONODES];
    __shared__ __align__(16) float wsm[2][16 * 128];
    __shared__ float vals[ONODES][128];
    __shared__ float mus[ONODES], ivs[ONODES];

    {
        const float4* vsrc = (const float4*)vin + blockIdx.x * 96;
        float4* vdst = (float4*)(out + N_NODES * NS) + blockIdx.x * 96;
        if (t < 96) vdst[t] = vsrc[t];
    }

    for (int idx = t; idx < HD * ONODES; idx += 128) {
        const int j = idx & 7;
        const int i = idx >> 3;
        a_t[i][j] = g_attn[(nb + j) * HD + i];
    }

    const float bov = bo[t];
    u64 acc[4];
#pragma unroll
    for (int jj = 0; jj < 4; jj++) acc[jj] = pack2(bov, bov);

    {
        const uint32_t b0a = smem_u32(wsm[0]);
#pragma unroll
        for (int p = 0; p < 4; p++)
            cp16(b0a + (t + p * 128) * 16, (const float4*)Wo + t + p * 128);
        cp_commit();
    }
    for (int kt = 0; kt < 8; kt++) {
        if (kt < 7) {
            const uint32_t d0 = smem_u32(wsm[(kt + 1) & 1]);
            const float4* so4 = (const float4*)(Wo + (kt + 1) * 2048);
#pragma unroll
            for (int p = 0; p < 4; p++)
                cp16(d0 + (t + p * 128) * 16, so4 + t + p * 128);
            cp_commit();
            cp_wait<1>();
        } else {
            cp_wait<0>();
        }
        __syncthreads();
        const int b = kt & 1;
#pragma unroll
        for (int ii = 0; ii < 16; ii++) {
            const int i = kt * 16 + ii;
            const float wv = wsm[b][ii * 128 + t];
            const u64 w2 = pack2(wv, wv);
            const ulonglong2* cr = (const ulonglong2*)a_t[i];
            const ulonglong2 ca = cr[0], cb = cr[1];
            acc[0] = fma2(w2, ca.x, acc[0]); acc[1] = fma2(w2, ca.y, acc[1]);
            acc[2] = fma2(w2, cb.x, acc[2]); acc[3] = fma2(w2, cb.y, acc[3]);
        }
        __syncthreads();
    }

    float val[8];
#pragma unroll
    for (int jj = 0; jj < 4; jj++) unpack2(acc[jj], val[2 * jj], val[2 * jj + 1]);
#pragma unroll
    for (int j = 0; j < 8; j++) {
        val[j] += s[(nb + j) * NS + t];
        vals[j][t] = val[j];
    }
    __syncthreads();

#pragma unroll
    for (int jj = 0; jj < 2; jj++) {
        const int j = w * 2 + jj;
        float sv = 0.f, sq = 0.f;
#pragma unroll
        for (int c = 0; c < 4; c++) {
            const float x = vals[j][lane + 32 * c];
            sv += x;
            sq = fmaf(x, x, sq);
        }
#pragma unroll
        for (int off = 16; off > 0; off >>= 1) {
            sv += __shfl_xor_sync(0xffffffffu, sv, off);
            sq += __shfl_xor_sync(0xffffffffu, sq, off);
        }
        if (lane == 0) {
            const float mu = sv * (1.f / 128.f);
            mus[j] = mu;
            ivs[j] = rsqrtf(sq * (1.f / 128.f) - mu * mu + 1e-5f);
        }
    }
    __syncthreads();

    const float gm = gamma[t], bt = beta[t];
#pragma unroll
    for (int j = 0; j < 8; j++) {
        out[(nb + j) * NS + t] = (val[j] - mus[j]) * ivs[j] * gm + bt;
    }
}

// ---------------------------------------------------------------------------
extern "C" void kernel_launch(void* const* d_in, const int* in_sizes, int n_in,
                              void* d_out, int out_size) {
    const float* s     = (const float*)d_in[0];
    const float* v     = (const float*)d_in[1];
    const float* Wq    = (const float*)d_in[2];
    const float* bq    = (const float*)d_in[3];
    const float* Wk    = (const float*)d_in[4];
    const float* bk    = (const float*)d_in[5];
    const float* Wv    = (const float*)d_in[6];
    const float* bv    = (const float*)d_in[7];
    const float* Wo    = (const float*)d_in[8];
    const float* bo    = (const float*)d_in[9];
    const float* gamma = (const float*)d_in[10];
    const float* beta  = (const float*)d_in[11];
    float* out = (float*)d_out;

    convw_kernel<<<256, 144>>>(Wq, Wk, Wv);
    proj_kernel<<<N_NODES / 32, 256>>>(s, v, bq, bk, bv);
    attn_kernel<<<dim3(N_NODES / 64, H), 256>>>();
    out_kernel<<<N_NODES / ONODES, 128>>>(s, v, Wo, bo, gamma, beta, out);
}

// round 12
// speedup vs baseline: 1.3805x; 1.0133x over previous
#include <cuda_runtime.h>
#include <cuda_fp16.h>
#include <cstdint>

#define N_NODES 4096
#define NS 128
#define NV 16
#define H 8
#define D 16
#define COMB 144
#define HD 128   // H*D

typedef unsigned long long u64;

// ---- f16 mma, fp32 accumulate ----
__device__ __forceinline__ void mma_f16(float* d, const uint32_t* a, uint32_t b0, uint32_t b1) {
    asm("mma.sync.aligned.m16n8k16.row.col.f32.f16.f16.f32 "
        "{%0,%1,%2,%3},{%4,%5,%6,%7},{%8,%9},{%0,%1,%2,%3};"
        : "+f"(d[0]), "+f"(d[1]), "+f"(d[2]), "+f"(d[3])
        : "r"(a[0]), "r"(a[1]), "r"(a[2]), "r"(a[3]), "r"(b0), "r"(b1));
}
// ---- f16 mma, f16 accumulate (attn scores) ----
__device__ __forceinline__ void mma_f16_s(uint32_t& d0, uint32_t& d1, const uint32_t* a,
                                          uint32_t b0, uint32_t b1) {
    asm("mma.sync.aligned.m16n8k16.row.col.f16.f16.f16.f16 "
        "{%0,%1},{%2,%3,%4,%5},{%6,%7},{%8,%9};"
        : "=r"(d0), "=r"(d1)
        : "r"(a[0]), "r"(a[1]), "r"(a[2]), "r"(a[3]), "r"(b0), "r"(b1),
          "r"(0u), "r"(0u));
}
__device__ __forceinline__ uint32_t h2bits(__half2 h) {
    return *reinterpret_cast<uint32_t*>(&h);
}
__device__ __forceinline__ __half2 bits2h(uint32_t u) {
    return *reinterpret_cast<__half2*>(&u);
}
// ---- cp.async ----
__device__ __forceinline__ uint32_t smem_u32(const void* p) {
    uint32_t a;
    asm("{ .reg .u64 t; cvta.to.shared.u64 t, %1; cvt.u32.u64 %0, t; }" : "=r"(a) : "l"(p));
    return a;
}
__device__ __forceinline__ void cp16(uint32_t smem_dst, const void* gsrc) {
    asm volatile("cp.async.cg.shared.global [%0], [%1], 16;" :: "r"(smem_dst), "l"(gsrc));
}
__device__ __forceinline__ void cp_commit() { asm volatile("cp.async.commit_group;"); }
template <int N>
__device__ __forceinline__ void cp_wait() {
    asm volatile("cp.async.wait_group %0;" :: "n"(N) : "memory");
}
__device__ __forceinline__ void barx(int id) {
    asm volatile("bar.sync %0, 128;" :: "r"(id) : "memory");
}

// Scratch (static device globals)
__device__ __half g_qh[N_NODES * HD];     // q * (D^-0.5 * log2e)
__device__ __half g_kh[N_NODES * HD];
__device__ __half g_vth[HD * N_NODES];    // v TRANSPOSED [ch][node]
__device__ __half g_attn_h[N_NODES * HD]; // attention output O, f16
__device__ __half g_Wqk_t[256 * COMB];    // TRANSPOSED [n=q|k][k=144]
__device__ __half g_Wv_t[HD * NS];        // TRANSPOSED [n][k]
__device__ __half g_Wo_t[NS * HD];        // TRANSPOSED [n][k]

// ---------------------------------------------------------------------------
// Kernel 0: one-off f32 -> f16 TRANSPOSED weight conversion.
// ---------------------------------------------------------------------------
__global__ void convw_kernel(const float* __restrict__ Wq, const float* __restrict__ Wk,
                             const float* __restrict__ Wv, const float* __restrict__ Wo) {
    const int n = blockIdx.x;     // 0..255
    const int k = threadIdx.x;    // 0..143
    const float w = (n < 128) ? Wq[k * 128 + n] : Wk[k * 128 + (n - 128)];
    g_Wqk_t[n * COMB + k] = __float2half(w);
    if (n < 128 && k < 128) {
        g_Wv_t[n * NS + k] = __float2half(Wv[k * 128 + n]);
        g_Wo_t[n * HD + k] = __float2half(Wo[k * 128 + n]);
    }
}

// ---------------------------------------------------------------------------
// Kernel 1: tensor-core projections (R11, unchanged — proven fragments).
// ---------------------------------------------------------------------------
#define SA 168    // comb stride in halves (84 words)
#define SWT 12    // weight-tile stride in words per n-row
#define SV 138
__global__ __launch_bounds__(256) void proj_kernel(
        const float* __restrict__ s, const float* __restrict__ v,
        const float* __restrict__ bq, const float* __restrict__ bk,
        const float* __restrict__ bv) {
    const int nb = blockIdx.x * 32;
    const int t = threadIdx.x;
    const int w = t >> 5, lane = t & 31;
    const int mw = w >> 2, nw = w & 3;
    const int g = lane >> 2, tid = lane & 3;
    const int m0 = mw * 16;

    __shared__ __align__(16) __half comb[32 * SA];
    __shared__ __align__(16) uint32_t wtb[2][256 * SWT];
    __shared__ __align__(16) __half vsm[32 * SV];

    for (int i = t; i < 32 * 32; i += 256) {
        const int node = i >> 5, c4 = i & 31;
        const float4 s4 = ((const float4*)(s + (nb + node) * NS))[c4];
        __half2* dst = (__half2*)(comb + node * SA + c4 * 4);
        dst[0] = __floats2half2_rn(s4.x, s4.y);
        dst[1] = __floats2half2_rn(s4.z, s4.w);
    }
    for (int i = t; i < 32 * NV; i += 256) {
        const int node = i >> 4, vi = i & 15;
        const float* vp = v + (nb + node) * NV * 3 + vi * 3;
        const float x = vp[0], y = vp[1], z = vp[2];
        comb[node * SA + 128 + vi] = __float2half(sqrtf(fmaxf(x * x + y * y + z * z, 1e-8f)));
    }

    const uint32_t* cw = (const uint32_t*)comb;
    const uint32_t wb[2] = { smem_u32(wtb[0]), smem_u32(wtb[1]) };

    float cq[8][4];
#pragma unroll
    for (int i = 0; i < 8; i++)
#pragma unroll
        for (int j = 0; j < 4; j++) cq[i][j] = 0.f;

    {
#pragma unroll
        for (int p = 0; p < 2; p++) {
            const int cid = t + p * 256;
            const int r = cid >> 1, hf = cid & 1;
            cp16(wb[0] + r * 48 + hf * 16,
                 (const char*)g_Wqk_t + r * (COMB * 2) + hf * 16);
        }
        cp_commit();
    }
    __syncthreads();

    for (int ks = 0; ks < 9; ks++) {
        if (ks < 8) {
            const uint32_t dst = wb[(ks + 1) & 1];
#pragma unroll
            for (int p = 0; p < 2; p++) {
                const int cid = t + p * 256;
                const int r = cid >> 1, hf = cid & 1;
                cp16(dst + r * 48 + hf * 16,
                     (const char*)g_Wqk_t + r * (COMB * 2) + (ks + 1) * 32 + hf * 16);
            }
            cp_commit();
            cp_wait<1>();
        } else {
            cp_wait<0>();
        }
        __syncthreads();
        const uint32_t* wt = wtb[ks & 1];

        uint32_t a[4];
        a[0] = cw[(m0 + g) * 84 + ks * 8 + tid];
        a[1] = cw[(m0 + g + 8) * 84 + ks * 8 + tid];
        a[2] = cw[(m0 + g) * 84 + ks * 8 + 4 + tid];
        a[3] = cw[(m0 + g + 8) * 84 + ks * 8 + 4 + tid];
#pragma unroll
        for (int bt = 0; bt < 8; bt++) {
            const uint32_t* br = wt + (nw * 64 + bt * 8 + g) * SWT;
            mma_f16(cq[bt], a, br[tid], br[4 + tid]);
        }
        __syncthreads();
    }

    {
        const float* barr = (nw < 2) ? bq : bk;
        const float scale = (nw < 2) ? 0.25f * 1.4426950408889634f : 1.0f;
        __half* dst = (nw < 2) ? g_qh : g_kh;
#pragma unroll
        for (int bt = 0; bt < 8; bt++) {
            const int c = nw * 64 + bt * 8 + 2 * tid;
            const int cl = c & 127;
            const float b0 = barr[cl], b1 = barr[cl + 1];
            const int r0 = nb + m0 + g;
            *(__half2*)(dst + r0 * HD + cl) =
                __floats2half2_rn((cq[bt][0] + b0) * scale, (cq[bt][1] + b1) * scale);
            *(__half2*)(dst + (r0 + 8) * HD + cl) =
                __floats2half2_rn((cq[bt][2] + b0) * scale, (cq[bt][3] + b1) * scale);
        }
    }

    float cv[4][4];
#pragma unroll
    for (int i = 0; i < 4; i++)
#pragma unroll
        for (int j = 0; j < 4; j++) cv[i][j] = 0.f;

    {
        const int r = t >> 1, hf = t & 1;
        cp16(wb[0] + r * 48 + hf * 16,
             (const char*)g_Wv_t + r * (NS * 2) + hf * 16);
        cp_commit();
    }
    for (int ks = 0; ks < 8; ks++) {
        if (ks < 7) {
            const uint32_t dst = wb[(ks + 1) & 1];
            const int r = t >> 1, hf = t & 1;
            cp16(dst + r * 48 + hf * 16,
                 (const char*)g_Wv_t + r * (NS * 2) + (ks + 1) * 32 + hf * 16);
            cp_commit();
            cp_wait<1>();
        } else {
            cp_wait<0>();
        }
        __syncthreads();
        const uint32_t* wt = wtb[ks & 1];

        uint32_t a[4];
        a[0] = cw[(m0 + g) * 84 + ks * 8 + tid];
        a[1] = cw[(m0 + g + 8) * 84 + ks * 8 + tid];
        a[2] = cw[(m0 + g) * 84 + ks * 8 + 4 + tid];
        a[3] = cw[(m0 + g + 8) * 84 + ks * 8 + 4 + tid];
#pragma unroll
        for (int bt = 0; bt < 4; bt++) {
            const uint32_t* br = wt + (nw * 32 + bt * 8 + g) * SWT;
            mma_f16(cv[bt], a, br[tid], br[4 + tid]);
        }
        __syncthreads();
    }

#pragma unroll
    for (int bt = 0; bt < 4; bt++) {
        const int c = nw * 32 + bt * 8 + 2 * tid;
        const float b0 = bv[c], b1 = bv[c + 1];
        const int r0 = m0 + g;
        *(__half2*)(vsm + r0 * SV + c)       = __floats2half2_rn(cv[bt][0] + b0, cv[bt][1] + b1);
        *(__half2*)(vsm + (r0 + 8) * SV + c) = __floats2half2_rn(cv[bt][2] + b0, cv[bt][3] + b1);
    }
    __syncthreads();
    {
        const int d = t >> 1;
        const int npart = (t & 1) * 16;
#pragma unroll
        for (int i = 0; i < 8; i++) {
            const int node = npart + i * 2;
            __half2 p;
            p.x = vsm[node * SV + d];
            p.y = vsm[(node + 1) * SV + d];
            *(__half2*)(g_vth + d * N_NODES + nb + node) = p;
        }
    }
}

// ---------------------------------------------------------------------------
// Kernel 2: f16 mma flash attention (R9/R11 champion; O stored as f16 now).
// ---------------------------------------------------------------------------
__global__ void attn_kernel() {
    const int h = blockIdx.y;
    const int qbase = blockIdx.x * 64;
    const int gid = threadIdx.x >> 7;
    const int tl = threadIdx.x & 127;
    const int w = tl >> 5;
    const int lane = tl & 31;
    const int g = lane >> 2;
    const int tid = lane & 3;

    __shared__ __align__(16) uint32_t Ksw[2][2][128 * 12];
    __shared__ __align__(16) uint32_t Vsw[2][2][16 * 68];
    __shared__ float mrg[128][10];

    uint32_t qa[4];
    {
        const __half* Q0 = g_qh + (qbase + w * 16 + g) * HD + h * D;
        const __half* Q1 = Q0 + 8 * HD;
        qa[0] = *(const uint32_t*)(Q0 + 2 * tid);
        qa[1] = *(const uint32_t*)(Q1 + 2 * tid);
        qa[2] = *(const uint32_t*)(Q0 + 2 * tid + 8);
        qa[3] = *(const uint32_t*)(Q1 + 2 * tid + 8);
    }

    float o0[4] = {0.f, 0.f, 0.f, 0.f};
    float o1[4] = {0.f, 0.f, 0.f, 0.f};
    float l0 = 0.f, l1 = 0.f;

    const int vrow = tl & 15;
    const int vchunk = tl >> 4;
    const uint32_t kdst0 = smem_u32(Ksw[gid][0]) + tl * 48;
    const uint32_t kdst1 = smem_u32(Ksw[gid][1]) + tl * 48;
    const uint32_t vdst0 = smem_u32(Vsw[gid][0]) + (vrow * 68 + vchunk * 8) * 4;
    const uint32_t vdst1 = smem_u32(Vsw[gid][1]) + (vrow * 68 + vchunk * 8) * 4;

    {
        const int kt = gid * 128;
        const __half* kp = g_kh + (kt + tl) * HD + h * D;
        cp16(kdst0, kp);
        cp16(kdst0 + 16, kp + 8);
        const __half* vp = g_vth + (h * D + vrow) * N_NODES + kt + vchunk * 16;
        cp16(vdst0, vp);
        cp16(vdst0 + 16, vp + 8);
        cp_commit();
    }

    for (int i = 0; i < 16; i++) {
        const int b = i & 1;
        if (i < 15) {
            const int kt = (2 * (i + 1) + gid) * 128;
            const uint32_t kd = b ? kdst0 : kdst1;
            const uint32_t vd = b ? vdst0 : vdst1;
            const __half* kp = g_kh + (kt + tl) * HD + h * D;
            cp16(kd, kp);
            cp16(kd + 16, kp + 8);
            const __half* vp = g_vth + (h * D + vrow) * N_NODES + kt + vchunk * 16;
            cp16(vd, vp);
            cp16(vd + 16, vp + 8);
            cp_commit();
            cp_wait<1>();
        } else {
            cp_wait<0>();
        }
        barx(1 + gid);

        const uint32_t* Kg = Ksw[gid][b];
        const uint32_t* Vg = Vsw[gid][b];
        __half2 lh0 = __half2half2(__float2half(0.f));
        __half2 lh1 = lh0;
#pragma unroll
        for (int u = 0; u < 8; u++) {
            uint32_t sA0, sA1, sB0, sB1;
            const int kA = (16 * u + g) * 12;
            const int kB = (16 * u + 8 + g) * 12;
            mma_f16_s(sA0, sA1, qa, Kg[kA + tid], Kg[kA + 4 + tid]);
            mma_f16_s(sB0, sB1, qa, Kg[kB + tid], Kg[kB + 4 + tid]);
            const __half2 e0 = h2exp2(bits2h(sA0));
            const __half2 e1 = h2exp2(bits2h(sA1));
            const __half2 e2 = h2exp2(bits2h(sB0));
            const __half2 e3 = h2exp2(bits2h(sB1));
            lh0 = __hadd2(lh0, __hadd2(e0, e2));
            lh1 = __hadd2(lh1, __hadd2(e1, e3));
            uint32_t pa[4];
            pa[0] = h2bits(e0);
            pa[1] = h2bits(e1);
            pa[2] = h2bits(e2);
            pa[3] = h2bits(e3);
            const int vb = 8 * u + tid;
            mma_f16(o0, pa, Vg[g * 68 + vb],       Vg[g * 68 + 4 + vb]);
            mma_f16(o1, pa, Vg[(g + 8) * 68 + vb], Vg[(g + 8) * 68 + 4 + vb]);
        }
        const float2 f0 = __half22float2(lh0);
        const float2 f1 = __half22float2(lh1);
        l0 += f0.x + f0.y;
        l1 += f1.x + f1.y;

        barx(1 + gid);
    }

    l0 += __shfl_xor_sync(0xffffffffu, l0, 1);
    l0 += __shfl_xor_sync(0xffffffffu, l0, 2);
    l1 += __shfl_xor_sync(0xffffffffu, l1, 1);
    l1 += __shfl_xor_sync(0xffffffffu, l1, 2);

    if (gid == 1) {
        float* m = mrg[tl];
        m[0] = o0[0]; m[1] = o0[1]; m[2] = o0[2]; m[3] = o0[3];
        m[4] = o1[0]; m[5] = o1[1]; m[6] = o1[2]; m[7] = o1[3];
        m[8] = l0; m[9] = l1;
    }
    __syncthreads();
    if (gid == 0) {
        const float* m = mrg[tl];
        const float i0 = 1.f / (l0 + m[8]);
        const float i1 = 1.f / (l1 + m[9]);
        __half* O0 = g_attn_h + (qbase + w * 16 + g) * HD + h * D;
        __half* O1 = O0 + 8 * HD;
        *(__half2*)(O0 + 2 * tid) =
            __floats2half2_rn((o0[0] + m[0]) * i0, (o0[1] + m[1]) * i0);
        *(__half2*)(O1 + 2 * tid) =
            __floats2half2_rn((o0[2] + m[2]) * i1, (o0[3] + m[3]) * i1);
        *(__half2*)(O0 + 2 * tid + 8) =
            __floats2half2_rn((o1[0] + m[4]) * i0, (o1[1] + m[5]) * i0);
        *(__half2*)(O1 + 2 * tid + 8) =
            __floats2half2_rn((o1[2] + m[6]) * i1, (o1[3] + m[7]) * i1);
    }
}

// ---------------------------------------------------------------------------
// Kernel 3: TENSOR-CORE out projection + residual + LayerNorm + v pass.
// Block = 32 nodes, 256 threads (proj's proven shape/fragments).
// GEMM: O_f16[32x128] @ Wo_t^T -> f32; residual preloaded f32-exact; LN
// per-warp (warp w owns nodes 4w..4w+3) via shuffle reductions.
// ---------------------------------------------------------------------------
__global__ __launch_bounds__(256) void out_kernel(
        const float* __restrict__ s, const float* __restrict__ vin,
        const float* __restrict__ bo,
        const float* __restrict__ gamma, const float* __restrict__ beta,
        float* __restrict__ out) {
    const int nb = blockIdx.x * 32;
    const int t = threadIdx.x;
    const int w = t >> 5, lane = t & 31;
    const int mw = w >> 2, nw = w & 3;
    const int g = lane >> 2, tid = lane & 3;
    const int m0 = mw * 16;

    __shared__ __align__(16) __half osm[32 * SA];        // O tile, stride 84 words
    __shared__ __align__(16) uint32_t wtb[2][128 * SWT]; // Wo k-slices
    __shared__ float vals[32 * 129];                     // s + attn_out (f32)
    __shared__ float mus[32], ivs[32];

    // v passthrough: 32 nodes -> 384 float4
    {
        const float4* vsrc = (const float4*)vin + blockIdx.x * 384;
        float4* vdst = (float4*)(out + N_NODES * NS) + blockIdx.x * 384;
        for (int i = t; i < 384; i += 256) vdst[i] = vsrc[i];
    }
    // preload residual s (f32, coalesced)
    for (int i = t; i < 32 * 128; i += 256) {
        const int node = i >> 7, c = i & 127;
        vals[node * 129 + c] = s[(nb + node) * NS + c];
    }

    const uint32_t ob = smem_u32(osm);
    const uint32_t wb[2] = { smem_u32(wtb[0]), smem_u32(wtb[1]) };

    // stage O tile (32 rows x 256B) + Wo k-step 0 in one group
    {
        for (int i = t; i < 512; i += 256) {
            const int r = i >> 4, c = i & 15;
            cp16(ob + r * 336 + c * 16, g_attn_h + (nb + r) * HD + c * 8);
        }
        const int r = t >> 1, hf = t & 1;
        cp16(wb[0] + r * 48 + hf * 16, (const char*)g_Wo_t + r * (HD * 2) + hf * 16);
        cp_commit();
    }

    const uint32_t* cw = (const uint32_t*)osm;
    float cq[4][4];
#pragma unroll
    for (int i = 0; i < 4; i++)
#pragma unroll
        for (int j = 0; j < 4; j++) cq[i][j] = 0.f;

    for (int ks = 0; ks < 8; ks++) {
        if (ks < 7) {
            const uint32_t dst = wb[(ks + 1) & 1];
            const int r = t >> 1, hf = t & 1;
            cp16(dst + r * 48 + hf * 16,
                 (const char*)g_Wo_t + r * (HD * 2) + (ks + 1) * 32 + hf * 16);
            cp_commit();
            cp_wait<1>();
        } else {
            cp_wait<0>();
        }
        __syncthreads();
        const uint32_t* wt = wtb[ks & 1];

        uint32_t a[4];
        a[0] = cw[(m0 + g) * 84 + ks * 8 + tid];
        a[1] = cw[(m0 + g + 8) * 84 + ks * 8 + tid];
        a[2] = cw[(m0 + g) * 84 + ks * 8 + 4 + tid];
        a[3] = cw[(m0 + g + 8) * 84 + ks * 8 + 4 + tid];
#pragma unroll
        for (int bt = 0; bt < 4; bt++) {
            const uint32_t* br = wt + (nw * 32 + bt * 8 + g) * SWT;
            mma_f16(cq[bt], a, br[tid], br[4 + tid]);
        }
        __syncthreads();
    }

    // epilogue: vals += attn_out + bias (f32 exact residual already loaded)
#pragma unroll
    for (int bt = 0; bt < 4; bt++) {
        const int c = nw * 32 + bt * 8 + 2 * tid;
        const float b0 = bo[c], b1 = bo[c + 1];
        const int r0 = m0 + g;
        vals[r0 * 129 + c]           += cq[bt][0] + b0;
        vals[r0 * 129 + c + 1]       += cq[bt][1] + b1;
        vals[(r0 + 8) * 129 + c]     += cq[bt][2] + b0;
        vals[(r0 + 8) * 129 + c + 1] += cq[bt][3] + b1;
    }
    __syncthreads();

    // LayerNorm stats: warp w owns nodes 4w .. 4w+3
#pragma unroll
    for (int jj = 0; jj < 4; jj++) {
        const int j = w * 4 + jj;
        float sv = 0.f, sq = 0.f;
#pragma unroll
        for (int c = 0; c < 4; c++) {
            const float x = vals[j * 129 + lane + 32 * c];
            sv += x;
            sq = fmaf(x, x, sq);
        }
#pragma unroll
        for (int off = 16; off > 0; off >>= 1) {
            sv += __shfl_xor_sync(0xffffffffu, sv, off);
            sq += __shfl_xor_sync(0xffffffffu, sq, off);
        }
        if (lane == 0) {
            const float mu = sv * (1.f / 128.f);
            mus[j] = mu;
            ivs[j] = rsqrtf(sq * (1.f / 128.f) - mu * mu + 1e-5f);
        }
    }
    __syncthreads();

    for (int i = t; i < 32 * 128; i += 256) {
        const int node = i >> 7, c = i & 127;
        out[(nb + node) * NS + c] =
            (vals[node * 129 + c] - mus[node]) * ivs[node] * gamma[c] + beta[c];
    }
}

// ---------------------------------------------------------------------------
extern "C" void kernel_launch(void* const* d_in, const int* in_sizes, int n_in,
                              void* d_out, int out_size) {
    const float* s     = (const float*)d_in[0];
    const float* v     = (const float*)d_in[1];
    const float* Wq    = (const float*)d_in[2];
    const float* bq    = (const float*)d_in[3];
    const float* Wk    = (const float*)d_in[4];
    const float* bk    = (const float*)d_in[5];
    const float* Wv    = (const float*)d_in[6];
    const float* bv    = (const float*)d_in[7];
    const float* Wo    = (const float*)d_in[8];
    const float* bo    = (const float*)d_in[9];
    const float* gamma = (const float*)d_in[10];
    const float* beta  = (const float*)d_in[11];
    float* out = (float*)d_out;

    convw_kernel<<<256, 144>>>(Wq, Wk, Wv, Wo);
    proj_kernel<<<N_NODES / 32, 256>>>(s, v, bq, bk, bv);
    attn_kernel<<<dim3(N_NODES / 64, H), 256>>>();
    out_kernel<<<N_NODES / 32, 256>>>(s, v, bo, gamma, beta, out);
}

// round 13
// speedup vs baseline: 1.3886x; 1.0059x over previous
#include <cuda_runtime.h>
#include <cuda_fp16.h>
#include <cstdint>

#define N_NODES 4096
#define NS 128
#define NV 16
#define H 8
#define D 16
#define COMB 144
#define HD 128   // H*D

typedef unsigned long long u64;

// ---- f16 mma, fp32 accumulate ----
__device__ __forceinline__ void mma_f16(float* d, const uint32_t* a, uint32_t b0, uint32_t b1) {
    asm("mma.sync.aligned.m16n8k16.row.col.f32.f16.f16.f32 "
        "{%0,%1,%2,%3},{%4,%5,%6,%7},{%8,%9},{%0,%1,%2,%3};"
        : "+f"(d[0]), "+f"(d[1]), "+f"(d[2]), "+f"(d[3])
        : "r"(a[0]), "r"(a[1]), "r"(a[2]), "r"(a[3]), "r"(b0), "r"(b1));
}
// ---- f16 mma, f16 accumulate (attn scores) ----
__device__ __forceinline__ void mma_f16_s(uint32_t& d0, uint32_t& d1, const uint32_t* a,
                                          uint32_t b0, uint32_t b1) {
    asm("mma.sync.aligned.m16n8k16.row.col.f16.f16.f16.f16 "
        "{%0,%1},{%2,%3,%4,%5},{%6,%7},{%8,%9};"
        : "=r"(d0), "=r"(d1)
        : "r"(a[0]), "r"(a[1]), "r"(a[2]), "r"(a[3]), "r"(b0), "r"(b1),
          "r"(0u), "r"(0u));
}
__device__ __forceinline__ uint32_t h2bits(__half2 h) {
    return *reinterpret_cast<uint32_t*>(&h);
}
__device__ __forceinline__ __half2 bits2h(uint32_t u) {
    return *reinterpret_cast<__half2*>(&u);
}
// ---- cp.async ----
__device__ __forceinline__ uint32_t smem_u32(const void* p) {
    uint32_t a;
    asm("{ .reg .u64 t; cvta.to.shared.u64 t, %1; cvt.u32.u64 %0, t; }" : "=r"(a) : "l"(p));
    return a;
}
__device__ __forceinline__ void cp16(uint32_t smem_dst, const void* gsrc) {
    asm volatile("cp.async.cg.shared.global [%0], [%1], 16;" :: "r"(smem_dst), "l"(gsrc));
}
__device__ __forceinline__ void cp_commit() { asm volatile("cp.async.commit_group;"); }
template <int N>
__device__ __forceinline__ void cp_wait() {
    asm volatile("cp.async.wait_group %0;" :: "n"(N) : "memory");
}
__device__ __forceinline__ void barx(int id) {
    asm volatile("bar.sync %0, 128;" :: "r"(id) : "memory");
}

// Scratch (static device globals)
__device__ __half g_qh[N_NODES * HD];     // q * (D^-0.5 * log2e)
__device__ __half g_kh[N_NODES * HD];
__device__ __half g_vth[HD * N_NODES];    // v TRANSPOSED [ch][node]
__device__ __half g_attn_h[N_NODES * HD]; // attention output O, f16
__device__ __half g_Wqk_t[256 * COMB];    // TRANSPOSED [n=q|k][k=144]
__device__ __half g_Wv_t[HD * NS];        // TRANSPOSED [n][k]
__device__ __half g_Wo_t[NS * HD];        // TRANSPOSED [n][k]

// ---------------------------------------------------------------------------
// Kernel 0: one-off f32 -> f16 TRANSPOSED weight conversion.
// ---------------------------------------------------------------------------
__global__ void convw_kernel(const float* __restrict__ Wq, const float* __restrict__ Wk,
                             const float* __restrict__ Wv, const float* __restrict__ Wo) {
    const int n = blockIdx.x;     // 0..255
    const int k = threadIdx.x;    // 0..143
    const float w = (n < 128) ? Wq[k * 128 + n] : Wk[k * 128 + (n - 128)];
    g_Wqk_t[n * COMB + k] = __float2half(w);
    if (n < 128 && k < 128) {
        g_Wv_t[n * NS + k] = __float2half(Wv[k * 128 + n]);
        g_Wo_t[n * HD + k] = __float2half(Wo[k * 128 + n]);
    }
}

// ---------------------------------------------------------------------------
// Kernel 1: tensor-core projections (R11/R12, unchanged — proven fragments).
// ---------------------------------------------------------------------------
#define SA 168    // comb stride in halves (84 words)
#define SWT 12    // weight-tile stride in words per n-row
#define SV 138
__global__ __launch_bounds__(256) void proj_kernel(
        const float* __restrict__ s, const float* __restrict__ v,
        const float* __restrict__ bq, const float* __restrict__ bk,
        const float* __restrict__ bv) {
    const int nb = blockIdx.x * 32;
    const int t = threadIdx.x;
    const int w = t >> 5, lane = t & 31;
    const int mw = w >> 2, nw = w & 3;
    const int g = lane >> 2, tid = lane & 3;
    const int m0 = mw * 16;

    __shared__ __align__(16) __half comb[32 * SA];
    __shared__ __align__(16) uint32_t wtb[2][256 * SWT];
    __shared__ __align__(16) __half vsm[32 * SV];

    for (int i = t; i < 32 * 32; i += 256) {
        const int node = i >> 5, c4 = i & 31;
        const float4 s4 = ((const float4*)(s + (nb + node) * NS))[c4];
        __half2* dst = (__half2*)(comb + node * SA + c4 * 4);
        dst[0] = __floats2half2_rn(s4.x, s4.y);
        dst[1] = __floats2half2_rn(s4.z, s4.w);
    }
    for (int i = t; i < 32 * NV; i += 256) {
        const int node = i >> 4, vi = i & 15;
        const float* vp = v + (nb + node) * NV * 3 + vi * 3;
        const float x = vp[0], y = vp[1], z = vp[2];
        comb[node * SA + 128 + vi] = __float2half(sqrtf(fmaxf(x * x + y * y + z * z, 1e-8f)));
    }

    const uint32_t* cw = (const uint32_t*)comb;
    const uint32_t wb[2] = { smem_u32(wtb[0]), smem_u32(wtb[1]) };

    float cq[8][4];
#pragma unroll
    for (int i = 0; i < 8; i++)
#pragma unroll
        for (int j = 0; j < 4; j++) cq[i][j] = 0.f;

    {
#pragma unroll
        for (int p = 0; p < 2; p++) {
            const int cid = t + p * 256;
            const int r = cid >> 1, hf = cid & 1;
            cp16(wb[0] + r * 48 + hf * 16,
                 (const char*)g_Wqk_t + r * (COMB * 2) + hf * 16);
        }
        cp_commit();
    }
    __syncthreads();

    for (int ks = 0; ks < 9; ks++) {
        if (ks < 8) {
            const uint32_t dst = wb[(ks + 1) & 1];
#pragma unroll
            for (int p = 0; p < 2; p++) {
                const int cid = t + p * 256;
                const int r = cid >> 1, hf = cid & 1;
                cp16(dst + r * 48 + hf * 16,
                     (const char*)g_Wqk_t + r * (COMB * 2) + (ks + 1) * 32 + hf * 16);
            }
            cp_commit();
            cp_wait<1>();
        } else {
            cp_wait<0>();
        }
        __syncthreads();
        const uint32_t* wt = wtb[ks & 1];

        uint32_t a[4];
        a[0] = cw[(m0 + g) * 84 + ks * 8 + tid];
        a[1] = cw[(m0 + g + 8) * 84 + ks * 8 + tid];
        a[2] = cw[(m0 + g) * 84 + ks * 8 + 4 + tid];
        a[3] = cw[(m0 + g + 8) * 84 + ks * 8 + 4 + tid];
#pragma unroll
        for (int bt = 0; bt < 8; bt++) {
            const uint32_t* br = wt + (nw * 64 + bt * 8 + g) * SWT;
            mma_f16(cq[bt], a, br[tid], br[4 + tid]);
        }
        __syncthreads();
    }

    {
        const float* barr = (nw < 2) ? bq : bk;
        const float scale = (nw < 2) ? 0.25f * 1.4426950408889634f : 1.0f;
        __half* dst = (nw < 2) ? g_qh : g_kh;
#pragma unroll
        for (int bt = 0; bt < 8; bt++) {
            const int c = nw * 64 + bt * 8 + 2 * tid;
            const int cl = c & 127;
            const float b0 = barr[cl], b1 = barr[cl + 1];
            const int r0 = nb + m0 + g;
            *(__half2*)(dst + r0 * HD + cl) =
                __floats2half2_rn((cq[bt][0] + b0) * scale, (cq[bt][1] + b1) * scale);
            *(__half2*)(dst + (r0 + 8) * HD + cl) =
                __floats2half2_rn((cq[bt][2] + b0) * scale, (cq[bt][3] + b1) * scale);
        }
    }

    float cv[4][4];
#pragma unroll
    for (int i = 0; i < 4; i++)
#pragma unroll
        for (int j = 0; j < 4; j++) cv[i][j] = 0.f;

    {
        const int r = t >> 1, hf = t & 1;
        cp16(wb[0] + r * 48 + hf * 16,
             (const char*)g_Wv_t + r * (NS * 2) + hf * 16);
        cp_commit();
    }
    for (int ks = 0; ks < 8; ks++) {
        if (ks < 7) {
            const uint32_t dst = wb[(ks + 1) & 1];
            const int r = t >> 1, hf = t & 1;
            cp16(dst + r * 48 + hf * 16,
                 (const char*)g_Wv_t + r * (NS * 2) + (ks + 1) * 32 + hf * 16);
            cp_commit();
            cp_wait<1>();
        } else {
            cp_wait<0>();
        }
        __syncthreads();
        const uint32_t* wt = wtb[ks & 1];

        uint32_t a[4];
        a[0] = cw[(m0 + g) * 84 + ks * 8 + tid];
        a[1] = cw[(m0 + g + 8) * 84 + ks * 8 + tid];
        a[2] = cw[(m0 + g) * 84 + ks * 8 + 4 + tid];
        a[3] = cw[(m0 + g + 8) * 84 + ks * 8 + 4 + tid];
#pragma unroll
        for (int bt = 0; bt < 4; bt++) {
            const uint32_t* br = wt + (nw * 32 + bt * 8 + g) * SWT;
            mma_f16(cv[bt], a, br[tid], br[4 + tid]);
        }
        __syncthreads();
    }

#pragma unroll
    for (int bt = 0; bt < 4; bt++) {
        const int c = nw * 32 + bt * 8 + 2 * tid;
        const float b0 = bv[c], b1 = bv[c + 1];
        const int r0 = m0 + g;
        *(__half2*)(vsm + r0 * SV + c)       = __floats2half2_rn(cv[bt][0] + b0, cv[bt][1] + b1);
        *(__half2*)(vsm + (r0 + 8) * SV + c) = __floats2half2_rn(cv[bt][2] + b0, cv[bt][3] + b1);
    }
    __syncthreads();
    {
        const int d = t >> 1;
        const int npart = (t & 1) * 16;
#pragma unroll
        for (int i = 0; i < 8; i++) {
            const int node = npart + i * 2;
            __half2 p;
            p.x = vsm[node * SV + d];
            p.y = vsm[(node + 1) * SV + d];
            *(__half2*)(g_vth + d * N_NODES + nb + node) = p;
        }
    }
}

// ---------------------------------------------------------------------------
// Kernel 2: f16 mma flash attention (R9/R12 champion, unchanged).
// ---------------------------------------------------------------------------
__global__ void attn_kernel() {
    const int h = blockIdx.y;
    const int qbase = blockIdx.x * 64;
    const int gid = threadIdx.x >> 7;
    const int tl = threadIdx.x & 127;
    const int w = tl >> 5;
    const int lane = tl & 31;
    const int g = lane >> 2;
    const int tid = lane & 3;

    __shared__ __align__(16) uint32_t Ksw[2][2][128 * 12];
    __shared__ __align__(16) uint32_t Vsw[2][2][16 * 68];
    __shared__ float mrg[128][10];

    uint32_t qa[4];
    {
        const __half* Q0 = g_qh + (qbase + w * 16 + g) * HD + h * D;
        const __half* Q1 = Q0 + 8 * HD;
        qa[0] = *(const uint32_t*)(Q0 + 2 * tid);
        qa[1] = *(const uint32_t*)(Q1 + 2 * tid);
        qa[2] = *(const uint32_t*)(Q0 + 2 * tid + 8);
        qa[3] = *(const uint32_t*)(Q1 + 2 * tid + 8);
    }

    float o0[4] = {0.f, 0.f, 0.f, 0.f};
    float o1[4] = {0.f, 0.f, 0.f, 0.f};
    float l0 = 0.f, l1 = 0.f;

    const int vrow = tl & 15;
    const int vchunk = tl >> 4;
    const uint32_t kdst0 = smem_u32(Ksw[gid][0]) + tl * 48;
    const uint32_t kdst1 = smem_u32(Ksw[gid][1]) + tl * 48;
    const uint32_t vdst0 = smem_u32(Vsw[gid][0]) + (vrow * 68 + vchunk * 8) * 4;
    const uint32_t vdst1 = smem_u32(Vsw[gid][1]) + (vrow * 68 + vchunk * 8) * 4;

    {
        const int kt = gid * 128;
        const __half* kp = g_kh + (kt + tl) * HD + h * D;
        cp16(kdst0, kp);
        cp16(kdst0 + 16, kp + 8);
        const __half* vp = g_vth + (h * D + vrow) * N_NODES + kt + vchunk * 16;
        cp16(vdst0, vp);
        cp16(vdst0 + 16, vp + 8);
        cp_commit();
    }

    for (int i = 0; i < 16; i++) {
        const int b = i & 1;
        if (i < 15) {
            const int kt = (2 * (i + 1) + gid) * 128;
            const uint32_t kd = b ? kdst0 : kdst1;
            const uint32_t vd = b ? vdst0 : vdst1;
            const __half* kp = g_kh + (kt + tl) * HD + h * D;
            cp16(kd, kp);
            cp16(kd + 16, kp + 8);
            const __half* vp = g_vth + (h * D + vrow) * N_NODES + kt + vchunk * 16;
            cp16(vd, vp);
            cp16(vd + 16, vp + 8);
            cp_commit();
            cp_wait<1>();
        } else {
            cp_wait<0>();
        }
        barx(1 + gid);

        const uint32_t* Kg = Ksw[gid][b];
        const uint32_t* Vg = Vsw[gid][b];
        __half2 lh0 = __half2half2(__float2half(0.f));
        __half2 lh1 = lh0;
#pragma unroll
        for (int u = 0; u < 8; u++) {
            uint32_t sA0, sA1, sB0, sB1;
            const int kA = (16 * u + g) * 12;
            const int kB = (16 * u + 8 + g) * 12;
            mma_f16_s(sA0, sA1, qa, Kg[kA + tid], Kg[kA + 4 + tid]);
            mma_f16_s(sB0, sB1, qa, Kg[kB + tid], Kg[kB + 4 + tid]);
            const __half2 e0 = h2exp2(bits2h(sA0));
            const __half2 e1 = h2exp2(bits2h(sA1));
            const __half2 e2 = h2exp2(bits2h(sB0));
            const __half2 e3 = h2exp2(bits2h(sB1));
            lh0 = __hadd2(lh0, __hadd2(e0, e2));
            lh1 = __hadd2(lh1, __hadd2(e1, e3));
            uint32_t pa[4];
            pa[0] = h2bits(e0);
            pa[1] = h2bits(e1);
            pa[2] = h2bits(e2);
            pa[3] = h2bits(e3);
            const int vb = 8 * u + tid;
            mma_f16(o0, pa, Vg[g * 68 + vb],       Vg[g * 68 + 4 + vb]);
            mma_f16(o1, pa, Vg[(g + 8) * 68 + vb], Vg[(g + 8) * 68 + 4 + vb]);
        }
        const float2 f0 = __half22float2(lh0);
        const float2 f1 = __half22float2(lh1);
        l0 += f0.x + f0.y;
        l1 += f1.x + f1.y;

        barx(1 + gid);
    }

    l0 += __shfl_xor_sync(0xffffffffu, l0, 1);
    l0 += __shfl_xor_sync(0xffffffffu, l0, 2);
    l1 += __shfl_xor_sync(0xffffffffu, l1, 1);
    l1 += __shfl_xor_sync(0xffffffffu, l1, 2);

    if (gid == 1) {
        float* m = mrg[tl];
        m[0] = o0[0]; m[1] = o0[1]; m[2] = o0[2]; m[3] = o0[3];
        m[4] = o1[0]; m[5] = o1[1]; m[6] = o1[2]; m[7] = o1[3];
        m[8] = l0; m[9] = l1;
    }
    __syncthreads();
    if (gid == 0) {
        const float* m = mrg[tl];
        const float i0 = 1.f / (l0 + m[8]);
        const float i1 = 1.f / (l1 + m[9]);
        __half* O0 = g_attn_h + (qbase + w * 16 + g) * HD + h * D;
        __half* O1 = O0 + 8 * HD;
        *(__half2*)(O0 + 2 * tid) =
            __floats2half2_rn((o0[0] + m[0]) * i0, (o0[1] + m[1]) * i0);
        *(__half2*)(O1 + 2 * tid) =
            __floats2half2_rn((o0[2] + m[2]) * i1, (o0[3] + m[3]) * i1);
        *(__half2*)(O0 + 2 * tid + 8) =
            __floats2half2_rn((o1[0] + m[4]) * i0, (o1[1] + m[5]) * i0);
        *(__half2*)(O1 + 2 * tid + 8) =
            __floats2half2_rn((o1[2] + m[6]) * i1, (o1[3] + m[7]) * i1);
    }
}

// ---------------------------------------------------------------------------
// Kernel 3: out projection, SINGLE-STAGE. Whole Wo (f16, 34.8KB) + O tile +
// residual staged in ONE cp.async group -> one __syncthreads -> 32 MMAs with
// no inner barriers -> epilogue + LN. Dynamic smem (62.3KB).
// Smem layout (bytes): osm[0, 10752) | Wo[10752, 45568) | vals[45568, 62080)
//                      | mus[62080, 62208) | ivs[62208, 62336)
// Wo rows stride 68 words (4g+tid banks — proven by attn's Vsw pattern).
// ---------------------------------------------------------------------------
#define OUT_SMEM 62336
__global__ __launch_bounds__(256) void out_kernel(
        const float* __restrict__ s, const float* __restrict__ vin,
        const float* __restrict__ bo,
        const float* __restrict__ gamma, const float* __restrict__ beta,
        float* __restrict__ out) {
    extern __shared__ __align__(16) char dsm[];
    __half* osm   = (__half*)dsm;                       // 32 x 84-word rows
    uint32_t* wo  = (uint32_t*)(dsm + 10752);           // 128 x 68-word rows
    float* vals   = (float*)(dsm + 45568);              // 32 x 129
    float* mus    = (float*)(dsm + 62080);
    float* ivs    = (float*)(dsm + 62208);

    const int nb = blockIdx.x * 32;
    const int t = threadIdx.x;
    const int w = t >> 5, lane = t & 31;
    const int mw = w >> 2, nw = w & 3;
    const int g = lane >> 2, tid = lane & 3;
    const int m0 = mw * 16;

    // v passthrough (independent of everything)
    {
        const float4* vsrc = (const float4*)vin + blockIdx.x * 384;
        float4* vdst = (float4*)(out + N_NODES * NS) + blockIdx.x * 384;
        for (int i = t; i < 384; i += 256) vdst[i] = vsrc[i];
    }

    // ONE staging group: O tile (512 chunks) + full Wo (2048 chunks)
    const uint32_t ob = smem_u32(osm);
    const uint32_t wb = smem_u32(wo);
    for (int i = t; i < 512; i += 256) {
        const int r = i >> 4, c = i & 15;
        cp16(ob + r * 336 + c * 16, g_attn_h + (nb + r) * HD + c * 8);
    }
    for (int i = t; i < 2048; i += 256) {
        const int r = i >> 4, c = i & 15;
        cp16(wb + r * 272 + c * 16, (const char*)g_Wo_t + r * 256 + c * 16);
    }
    cp_commit();

    // residual s (plain f32 loads overlap with cp.async in flight)
    for (int i = t; i < 32 * 128; i += 256) {
        const int node = i >> 7, c = i & 127;
        vals[node * 129 + c] = s[(nb + node) * NS + c];
    }

    cp_wait<0>();
    __syncthreads();

    // 32 warp-MMAs, zero inner barriers
    const uint32_t* cw = (const uint32_t*)osm;
    float cq[4][4];
#pragma unroll
    for (int i = 0; i < 4; i++)
#pragma unroll
        for (int j = 0; j < 4; j++) cq[i][j] = 0.f;

#pragma unroll
    for (int ks = 0; ks < 8; ks++) {
        uint32_t a[4];
        a[0] = cw[(m0 + g) * 84 + ks * 8 + tid];
        a[1] = cw[(m0 + g + 8) * 84 + ks * 8 + tid];
        a[2] = cw[(m0 + g) * 84 + ks * 8 + 4 + tid];
        a[3] = cw[(m0 + g + 8) * 84 + ks * 8 + 4 + tid];
#pragma unroll
        for (int bt = 0; bt < 4; bt++) {
            const uint32_t* br = wo + (nw * 32 + bt * 8 + g) * 68 + ks * 8;
            mma_f16(cq[bt], a, br[tid], br[4 + tid]);
        }
    }

    // epilogue: vals += attn_out + bias
#pragma unroll
    for (int bt = 0; bt < 4; bt++) {
        const int c = nw * 32 + bt * 8 + 2 * tid;
        const float b0 = bo[c], b1 = bo[c + 1];
        const int r0 = m0 + g;
        vals[r0 * 129 + c]           += cq[bt][0] + b0;
        vals[r0 * 129 + c + 1]       += cq[bt][1] + b1;
        vals[(r0 + 8) * 129 + c]     += cq[bt][2] + b0;
        vals[(r0 + 8) * 129 + c + 1] += cq[bt][3] + b1;
    }
    __syncthreads();

    // LayerNorm: warp w owns nodes 4w .. 4w+3
#pragma unroll
    for (int jj = 0; jj < 4; jj++) {
        const int j = w * 4 + jj;
        float sv = 0.f, sq = 0.f;
#pragma unroll
        for (int c = 0; c < 4; c++) {
            const float x = vals[j * 129 + lane + 32 * c];
            sv += x;
            sq = fmaf(x, x, sq);
        }
#pragma unroll
        for (int off = 16; off > 0; off >>= 1) {
            sv += __shfl_xor_sync(0xffffffffu, sv, off);
            sq += __shfl_xor_sync(0xffffffffu, sq, off);
        }
        if (lane == 0) {
            const float mu = sv * (1.f / 128.f);
            mus[j] = mu;
            ivs[j] = rsqrtf(sq * (1.f / 128.f) - mu * mu + 1e-5f);
        }
    }
    __syncthreads();

    for (int i = t; i < 32 * 128; i += 256) {
        const int node = i >> 7, c = i & 127;
        out[(nb + node) * NS + c] =
            (vals[node * 129 + c] - mus[node]) * ivs[node] * gamma[c] + beta[c];
    }
}

// ---------------------------------------------------------------------------
extern "C" void kernel_launch(void* const* d_in, const int* in_sizes, int n_in,
                              void* d_out, int out_size) {
    const float* s     = (const float*)d_in[0];
    const float* v     = (const float*)d_in[1];
    const float* Wq    = (const float*)d_in[2];
    const float* bq    = (const float*)d_in[3];
    const float* Wk    = (const float*)d_in[4];
    const float* bk    = (const float*)d_in[5];
    const float* Wv    = (const float*)d_in[6];
    const float* bv    = (const float*)d_in[7];
    const float* Wo    = (const float*)d_in[8];
    const float* bo    = (const float*)d_in[9];
    const float* gamma = (const float*)d_in[10];
    const float* beta  = (const float*)d_in[11];
    float* out = (float*)d_out;

    cudaFuncSetAttribute(out_kernel, cudaFuncAttributeMaxDynamicSharedMemorySize, OUT_SMEM);

    convw_kernel<<<256, 144>>>(Wq, Wk, Wv, Wo);
    proj_kernel<<<N_NODES / 32, 256>>>(s, v, bq, bk, bv);
    attn_kernel<<<dim3(N_NODES / 64, H), 256>>>();
    out_kernel<<<N_NODES / 32, 256, OUT_SMEM>>>(s, v, bo, gamma, beta, out);
}

// round 14
// speedup vs baseline: 1.5239x; 1.0975x over previous
#include <cuda_runtime.h>
#include <cuda_fp16.h>
#include <cstdint>

#define N_NODES 4096
#define NS 128
#define NV 16
#define H 8
#define D 16
#define COMB 144
#define HD 128   // H*D

typedef unsigned long long u64;

// ---- f16 mma, fp32 accumulate ----
__device__ __forceinline__ void mma_f16(float* d, const uint32_t* a, uint32_t b0, uint32_t b1) {
    asm("mma.sync.aligned.m16n8k16.row.col.f32.f16.f16.f32 "
        "{%0,%1,%2,%3},{%4,%5,%6,%7},{%8,%9},{%0,%1,%2,%3};"
        : "+f"(d[0]), "+f"(d[1]), "+f"(d[2]), "+f"(d[3])
        : "r"(a[0]), "r"(a[1]), "r"(a[2]), "r"(a[3]), "r"(b0), "r"(b1));
}
// ---- f16 mma, f16 accumulate (attn scores) ----
__device__ __forceinline__ void mma_f16_s(uint32_t& d0, uint32_t& d1, const uint32_t* a,
                                          uint32_t b0, uint32_t b1) {
    asm("mma.sync.aligned.m16n8k16.row.col.f16.f16.f16.f16 "
        "{%0,%1},{%2,%3,%4,%5},{%6,%7},{%8,%9};"
        : "=r"(d0), "=r"(d1)
        : "r"(a[0]), "r"(a[1]), "r"(a[2]), "r"(a[3]), "r"(b0), "r"(b1),
          "r"(0u), "r"(0u));
}
__device__ __forceinline__ uint32_t h2bits(__half2 h) {
    return *reinterpret_cast<uint32_t*>(&h);
}
__device__ __forceinline__ __half2 bits2h(uint32_t u) {
    return *reinterpret_cast<__half2*>(&u);
}
// ---- cp.async ----
__device__ __forceinline__ uint32_t smem_u32(const void* p) {
    uint32_t a;
    asm("{ .reg .u64 t; cvta.to.shared.u64 t, %1; cvt.u32.u64 %0, t; }" : "=r"(a) : "l"(p));
    return a;
}
__device__ __forceinline__ void cp16(uint32_t smem_dst, const void* gsrc) {
    asm volatile("cp.async.cg.shared.global [%0], [%1], 16;" :: "r"(smem_dst), "l"(gsrc));
}
__device__ __forceinline__ void cp_commit() { asm volatile("cp.async.commit_group;"); }
template <int N>
__device__ __forceinline__ void cp_wait() {
    asm volatile("cp.async.wait_group %0;" :: "n"(N) : "memory");
}

// Scratch (static device globals)
__device__ __half g_qh[N_NODES * HD];     // q * (D^-0.5 * log2e)
__device__ __half g_kh[N_NODES * HD];
__device__ __half g_vth[HD * N_NODES];    // v TRANSPOSED [ch][node]
__device__ __half g_attn_h[N_NODES * HD]; // attention output O, f16
__device__ __half g_Wqk_t[256 * COMB];    // TRANSPOSED [n=q|k][k=144]
__device__ __half g_Wv_t[HD * NS];        // TRANSPOSED [n][k]
__device__ __half g_Wo_t[NS * HD];        // TRANSPOSED [n][k]

// ---------------------------------------------------------------------------
// Kernel 0: one-off f32 -> f16 TRANSPOSED weight conversion.
// ---------------------------------------------------------------------------
__global__ void convw_kernel(const float* __restrict__ Wq, const float* __restrict__ Wk,
                             const float* __restrict__ Wv, const float* __restrict__ Wo) {
    const int n = blockIdx.x;     // 0..255
    const int k = threadIdx.x;    // 0..143
    const float w = (n < 128) ? Wq[k * 128 + n] : Wk[k * 128 + (n - 128)];
    g_Wqk_t[n * COMB + k] = __float2half(w);
    if (n < 128 && k < 128) {
        g_Wv_t[n * NS + k] = __float2half(Wv[k * 128 + n]);
        g_Wo_t[n * HD + k] = __float2half(Wo[k * 128 + n]);
    }
}

// ---------------------------------------------------------------------------
// Kernel 1: tensor-core projections (R11–R13, unchanged — proven fragments).
// ---------------------------------------------------------------------------
#define SA 168
#define SWT 12
#define SV 138
__global__ __launch_bounds__(256) void proj_kernel(
        const float* __restrict__ s, const float* __restrict__ v,
        const float* __restrict__ bq, const float* __restrict__ bk,
        const float* __restrict__ bv) {
    const int nb = blockIdx.x * 32;
    const int t = threadIdx.x;
    const int w = t >> 5, lane = t & 31;
    const int mw = w >> 2, nw = w & 3;
    const int g = lane >> 2, tid = lane & 3;
    const int m0 = mw * 16;

    __shared__ __align__(16) __half comb[32 * SA];
    __shared__ __align__(16) uint32_t wtb[2][256 * SWT];
    __shared__ __align__(16) __half vsm[32 * SV];

    for (int i = t; i < 32 * 32; i += 256) {
        const int node = i >> 5, c4 = i & 31;
        const float4 s4 = ((const float4*)(s + (nb + node) * NS))[c4];
        __half2* dst = (__half2*)(comb + node * SA + c4 * 4);
        dst[0] = __floats2half2_rn(s4.x, s4.y);
        dst[1] = __floats2half2_rn(s4.z, s4.w);
    }
    for (int i = t; i < 32 * NV; i += 256) {
        const int node = i >> 4, vi = i & 15;
        const float* vp = v + (nb + node) * NV * 3 + vi * 3;
        const float x = vp[0], y = vp[1], z = vp[2];
        comb[node * SA + 128 + vi] = __float2half(sqrtf(fmaxf(x * x + y * y + z * z, 1e-8f)));
    }

    const uint32_t* cw = (const uint32_t*)comb;
    const uint32_t wb[2] = { smem_u32(wtb[0]), smem_u32(wtb[1]) };

    float cq[8][4];
#pragma unroll
    for (int i = 0; i < 8; i++)
#pragma unroll
        for (int j = 0; j < 4; j++) cq[i][j] = 0.f;

    {
#pragma unroll
        for (int p = 0; p < 2; p++) {
            const int cid = t + p * 256;
            const int r = cid >> 1, hf = cid & 1;
            cp16(wb[0] + r * 48 + hf * 16,
                 (const char*)g_Wqk_t + r * (COMB * 2) + hf * 16);
        }
        cp_commit();
    }
    __syncthreads();

    for (int ks = 0; ks < 9; ks++) {
        if (ks < 8) {
            const uint32_t dst = wb[(ks + 1) & 1];
#pragma unroll
            for (int p = 0; p < 2; p++) {
                const int cid = t + p * 256;
                const int r = cid >> 1, hf = cid & 1;
                cp16(dst + r * 48 + hf * 16,
                     (const char*)g_Wqk_t + r * (COMB * 2) + (ks + 1) * 32 + hf * 16);
            }
            cp_commit();
            cp_wait<1>();
        } else {
            cp_wait<0>();
        }
        __syncthreads();
        const uint32_t* wt = wtb[ks & 1];

        uint32_t a[4];
        a[0] = cw[(m0 + g) * 84 + ks * 8 + tid];
        a[1] = cw[(m0 + g + 8) * 84 + ks * 8 + tid];
        a[2] = cw[(m0 + g) * 84 + ks * 8 + 4 + tid];
        a[3] = cw[(m0 + g + 8) * 84 + ks * 8 + 4 + tid];
#pragma unroll
        for (int bt = 0; bt < 8; bt++) {
            const uint32_t* br = wt + (nw * 64 + bt * 8 + g) * SWT;
            mma_f16(cq[bt], a, br[tid], br[4 + tid]);
        }
        __syncthreads();
    }

    {
        const float* barr = (nw < 2) ? bq : bk;
        const float scale = (nw < 2) ? 0.25f * 1.4426950408889634f : 1.0f;
        __half* dst = (nw < 2) ? g_qh : g_kh;
#pragma unroll
        for (int bt = 0; bt < 8; bt++) {
            const int c = nw * 64 + bt * 8 + 2 * tid;
            const int cl = c & 127;
            const float b0 = barr[cl], b1 = barr[cl + 1];
            const int r0 = nb + m0 + g;
            *(__half2*)(dst + r0 * HD + cl) =
                __floats2half2_rn((cq[bt][0] + b0) * scale, (cq[bt][1] + b1) * scale);
            *(__half2*)(dst + (r0 + 8) * HD + cl) =
                __floats2half2_rn((cq[bt][2] + b0) * scale, (cq[bt][3] + b1) * scale);
        }
    }

    float cv[4][4];
#pragma unroll
    for (int i = 0; i < 4; i++)
#pragma unroll
        for (int j = 0; j < 4; j++) cv[i][j] = 0.f;

    {
        const int r = t >> 1, hf = t & 1;
        cp16(wb[0] + r * 48 + hf * 16,
             (const char*)g_Wv_t + r * (NS * 2) + hf * 16);
        cp_commit();
    }
    for (int ks = 0; ks < 8; ks++) {
        if (ks < 7) {
            const uint32_t dst = wb[(ks + 1) & 1];
            const int r = t >> 1, hf = t & 1;
            cp16(dst + r * 48 + hf * 16,
                 (const char*)g_Wv_t + r * (NS * 2) + (ks + 1) * 32 + hf * 16);
            cp_commit();
            cp_wait<1>();
        } else {
            cp_wait<0>();
        }
        __syncthreads();
        const uint32_t* wt = wtb[ks & 1];

        uint32_t a[4];
        a[0] = cw[(m0 + g) * 84 + ks * 8 + tid];
        a[1] = cw[(m0 + g + 8) * 84 + ks * 8 + tid];
        a[2] = cw[(m0 + g) * 84 + ks * 8 + 4 + tid];
        a[3] = cw[(m0 + g + 8) * 84 + ks * 8 + 4 + tid];
#pragma unroll
        for (int bt = 0; bt < 4; bt++) {
            const uint32_t* br = wt + (nw * 32 + bt * 8 + g) * SWT;
            mma_f16(cv[bt], a, br[tid], br[4 + tid]);
        }
        __syncthreads();
    }

#pragma unroll
    for (int bt = 0; bt < 4; bt++) {
        const int c = nw * 32 + bt * 8 + 2 * tid;
        const float b0 = bv[c], b1 = bv[c + 1];
        const int r0 = m0 + g;
        *(__half2*)(vsm + r0 * SV + c)       = __floats2half2_rn(cv[bt][0] + b0, cv[bt][1] + b1);
        *(__half2*)(vsm + (r0 + 8) * SV + c) = __floats2half2_rn(cv[bt][2] + b0, cv[bt][3] + b1);
    }
    __syncthreads();
    {
        const int d = t >> 1;
        const int npart = (t & 1) * 16;
#pragma unroll
        for (int i = 0; i < 8; i++) {
            const int node = npart + i * 2;
            __half2 p;
            p.x = vsm[node * SV + d];
            p.y = vsm[(node + 1) * SV + d];
            *(__half2*)(g_vth + d * N_NODES + nb + node) = p;
        }
    }
}

// ---------------------------------------------------------------------------
// Kernel 2: f16 mma flash attention, 128 QUERIES/BLOCK, no split-K.
// 8 warps share each double-buffered 128-key K/V tile (staging traffic and
// barriers per key HALVED vs R9's 64-query split-K blocks). Each warp owns
// 16 query rows and walks all 4096 keys; l is complete per warp after the
// quad reduce (no merge phase). Fragments identical to R9 (proven).
// ---------------------------------------------------------------------------
__global__ __launch_bounds__(256) void attn_kernel() {
    const int h = blockIdx.y;
    const int qbase = blockIdx.x * 128;
    const int t = threadIdx.x;      // 0..255
    const int w = t >> 5;
    const int lane = t & 31;
    const int g = lane >> 2;
    const int tid = lane & 3;

    __shared__ __align__(16) uint32_t Ksw[2][128 * 12];
    __shared__ __align__(16) uint32_t Vsw[2][16 * 68];

    uint32_t qa[4];
    {
        const __half* Q0 = g_qh + (qbase + w * 16 + g) * HD + h * D;
        const __half* Q1 = Q0 + 8 * HD;
        qa[0] = *(const uint32_t*)(Q0 + 2 * tid);
        qa[1] = *(const uint32_t*)(Q1 + 2 * tid);
        qa[2] = *(const uint32_t*)(Q0 + 2 * tid + 8);
        qa[3] = *(const uint32_t*)(Q1 + 2 * tid + 8);
    }

    float o0[4] = {0.f, 0.f, 0.f, 0.f};
    float o1[4] = {0.f, 0.f, 0.f, 0.f};
    float l0 = 0.f, l1 = 0.f;

    // staging split: threads 0..127 stage K (key t, 2 chunks),
    //                threads 128..255 stage V (chunk pair)
    const bool stageK = (t < 128);
    const int sk_key = t & 127;
    const int sv_row = (t & 127) >> 3;        // 0..15
    const int sv_c   = (t & 7);               // 0..7 (8 chunks of 16B per row)
    const uint32_t kdst[2] = { smem_u32(Ksw[0]) + sk_key * 48,
                               smem_u32(Ksw[1]) + sk_key * 48 };
    const uint32_t vdst[2] = { smem_u32(Vsw[0]) + (sv_row * 68 + sv_c * 8) * 4,
                               smem_u32(Vsw[1]) + (sv_row * 68 + sv_c * 8) * 4 };

    // preload tile 0
    if (stageK) {
        const __half* kp = g_kh + sk_key * HD + h * D;
        cp16(kdst[0], kp);
        cp16(kdst[0] + 16, kp + 8);
    } else {
        const __half* vp = g_vth + (h * D + sv_row) * N_NODES + sv_c * 16;
        cp16(vdst[0], vp);
        cp16(vdst[0] + 16, vp + 8);
    }
    cp_commit();

    for (int i = 0; i < 32; i++) {
        const int b = i & 1;
        if (i < 31) {
            const int kt = (i + 1) * 128;
            const int nb_ = (i + 1) & 1;
            if (stageK) {
                const __half* kp = g_kh + (kt + sk_key) * HD + h * D;
                cp16(kdst[nb_], kp);
                cp16(kdst[nb_] + 16, kp + 8);
            } else {
                const __half* vp = g_vth + (h * D + sv_row) * N_NODES + kt + sv_c * 16;
                cp16(vdst[nb_], vp);
                cp16(vdst[nb_] + 16, vp + 8);
            }
            cp_commit();
            cp_wait<1>();
        } else {
            cp_wait<0>();
        }
        __syncthreads();

        const uint32_t* Kg = Ksw[b];
        const uint32_t* Vg = Vsw[b];
        __half2 lh0 = __half2half2(__float2half(0.f));
        __half2 lh1 = lh0;
#pragma unroll
        for (int u = 0; u < 8; u++) {
            uint32_t sA0, sA1, sB0, sB1;
            const int kA = (16 * u + g) * 12;
            const int kB = (16 * u + 8 + g) * 12;
            mma_f16_s(sA0, sA1, qa, Kg[kA + tid], Kg[kA + 4 + tid]);
            mma_f16_s(sB0, sB1, qa, Kg[kB + tid], Kg[kB + 4 + tid]);
            const __half2 e0 = h2exp2(bits2h(sA0));
            const __half2 e1 = h2exp2(bits2h(sA1));
            const __half2 e2 = h2exp2(bits2h(sB0));
            const __half2 e3 = h2exp2(bits2h(sB1));
            lh0 = __hadd2(lh0, __hadd2(e0, e2));
            lh1 = __hadd2(lh1, __hadd2(e1, e3));
            uint32_t pa[4];
            pa[0] = h2bits(e0);
            pa[1] = h2bits(e1);
            pa[2] = h2bits(e2);
            pa[3] = h2bits(e3);
            const int vb = 8 * u + tid;
            mma_f16(o0, pa, Vg[g * 68 + vb],       Vg[g * 68 + 4 + vb]);
            mma_f16(o1, pa, Vg[(g + 8) * 68 + vb], Vg[(g + 8) * 68 + 4 + vb]);
        }
        const float2 f0 = __half22float2(lh0);
        const float2 f1 = __half22float2(lh1);
        l0 += f0.x + f0.y;
        l1 += f1.x + f1.y;

        __syncthreads();   // all warps done with buf b before it is refilled
    }

    // quad-reduce row sums (complete: this warp saw all keys)
    l0 += __shfl_xor_sync(0xffffffffu, l0, 1);
    l0 += __shfl_xor_sync(0xffffffffu, l0, 2);
    l1 += __shfl_xor_sync(0xffffffffu, l1, 1);
    l1 += __shfl_xor_sync(0xffffffffu, l1, 2);
    const float i0 = 1.f / l0;
    const float i1 = 1.f / l1;

    __half* O0 = g_attn_h + (qbase + w * 16 + g) * HD + h * D;
    __half* O1 = O0 + 8 * HD;
    *(__half2*)(O0 + 2 * tid)     = __floats2half2_rn(o0[0] * i0, o0[1] * i0);
    *(__half2*)(O1 + 2 * tid)     = __floats2half2_rn(o0[2] * i1, o0[3] * i1);
    *(__half2*)(O0 + 2 * tid + 8) = __floats2half2_rn(o1[0] * i0, o1[1] * i0);
    *(__half2*)(O1 + 2 * tid + 8) = __floats2half2_rn(o1[2] * i1, o1[3] * i1);
}

// ---------------------------------------------------------------------------
// Kernel 3: out projection, 16 NODES/BLOCK (grid 256, 128 threads) so blocks
// overlap across SMs (R13's grid-128 single wave was the binder: occ 12.8%,
// issue 8.5%, all pipes idle). Single-stage staging, no inner barriers.
// Smem: osm[0,5376) | Wo[5376,40192) | vals[40192,48448) | mus/ivs.
// ---------------------------------------------------------------------------
#define OUT_SMEM 48640
__global__ __launch_bounds__(128) void out_kernel(
        const float* __restrict__ s, const float* __restrict__ vin,
        const float* __restrict__ bo,
        const float* __restrict__ gamma, const float* __restrict__ beta,
        float* __restrict__ out) {
    extern __shared__ __align__(16) char dsm[];
    __half* osm   = (__half*)dsm;               // 16 x 84-word rows
    uint32_t* wo  = (uint32_t*)(dsm + 5376);    // 128 x 68-word rows
    float* vals   = (float*)(dsm + 40192);      // 16 x 129
    float* mus    = (float*)(dsm + 48448);
    float* ivs    = (float*)(dsm + 48512);

    const int nb = blockIdx.x * 16;
    const int t = threadIdx.x;       // 0..127
    const int w = t >> 5, lane = t & 31;   // w = nw (4 warps, one n-slice each)
    const int g = lane >> 2, tid = lane & 3;

    // v passthrough: 16 nodes -> 192 float4
    {
        const float4* vsrc = (const float4*)vin + blockIdx.x * 192;
        float4* vdst = (float4*)(out + N_NODES * NS) + blockIdx.x * 192;
        for (int i = t; i < 192; i += 128) vdst[i] = vsrc[i];
    }

    // ONE staging group: O tile (256 chunks) + full Wo (2048 chunks)
    const uint32_t ob = smem_u32(osm);
    const uint32_t wb = smem_u32(wo);
    for (int i = t; i < 256; i += 128) {
        const int r = i >> 4, c = i & 15;
        cp16(ob + r * 336 + c * 16, g_attn_h + (nb + r) * HD + c * 8);
    }
    for (int i = t; i < 2048; i += 128) {
        const int r = i >> 4, c = i & 15;
        cp16(wb + r * 272 + c * 16, (const char*)g_Wo_t + r * 256 + c * 16);
    }
    cp_commit();

    // residual s (f32)
    for (int i = t; i < 16 * 128; i += 128) {
        const int node = i >> 7, c = i & 127;
        vals[node * 129 + c] = s[(nb + node) * NS + c];
    }

    cp_wait<0>();
    __syncthreads();

    const uint32_t* cw = (const uint32_t*)osm;
    float cq[4][4];
#pragma unroll
    for (int i = 0; i < 4; i++)
#pragma unroll
        for (int j = 0; j < 4; j++) cq[i][j] = 0.f;

#pragma unroll
    for (int ks = 0; ks < 8; ks++) {
        uint32_t a[4];
        a[0] = cw[g * 84 + ks * 8 + tid];
        a[1] = cw[(g + 8) * 84 + ks * 8 + tid];
        a[2] = cw[g * 84 + ks * 8 + 4 + tid];
        a[3] = cw[(g + 8) * 84 + ks * 8 + 4 + tid];
#pragma unroll
        for (int bt = 0; bt < 4; bt++) {
            const uint32_t* br = wo + (w * 32 + bt * 8 + g) * 68 + ks * 8;
            mma_f16(cq[bt], a, br[tid], br[4 + tid]);
        }
    }

    // epilogue: vals += attn_out + bias
#pragma unroll
    for (int bt = 0; bt < 4; bt++) {
        const int c = w * 32 + bt * 8 + 2 * tid;
        const float b0 = bo[c], b1 = bo[c + 1];
        vals[g * 129 + c]           += cq[bt][0] + b0;
        vals[g * 129 + c + 1]       += cq[bt][1] + b1;
        vals[(g + 8) * 129 + c]     += cq[bt][2] + b0;
        vals[(g + 8) * 129 + c + 1] += cq[bt][3] + b1;
    }
    __syncthreads();

    // LayerNorm: warp w owns nodes 4w .. 4w+3
#pragma unroll
    for (int jj = 0; jj < 4; jj++) {
        const int j = w * 4 + jj;
        float sv = 0.f, sq = 0.f;
#pragma unroll
        for (int c = 0; c < 4; c++) {
            const float x = vals[j * 129 + lane + 32 * c];
            sv += x;
            sq = fmaf(x, x, sq);
        }
#pragma unroll
        for (int off = 16; off > 0; off >>= 1) {
            sv += __shfl_xor_sync(0xffffffffu, sv, off);
            sq += __shfl_xor_sync(0xffffffffu, sq, off);
        }
        if (lane == 0) {
            const float mu = sv * (1.f / 128.f);
            mus[j] = mu;
            ivs[j] = rsqrtf(sq * (1.f / 128.f) - mu * mu + 1e-5f);
        }
    }
    __syncthreads();

    for (int i = t; i < 16 * 128; i += 128) {
        const int node = i >> 7, c = i & 127;
        out[(nb + node) * NS + c] =
            (vals[node * 129 + c] - mus[node]) * ivs[node] * gamma[c] + beta[c];
    }
}

// ---------------------------------------------------------------------------
extern "C" void kernel_launch(void* const* d_in, const int* in_sizes, int n_in,
                              void* d_out, int out_size) {
    const float* s     = (const float*)d_in[0];
    const float* v     = (const float*)d_in[1];
    const float* Wq    = (const float*)d_in[2];
    const float* bq    = (const float*)d_in[3];
    const float* Wk    = (const float*)d_in[4];
    const float* bk    = (const float*)d_in[5];
    const float* Wv    = (const float*)d_in[6];
    const float* bv    = (const float*)d_in[7];
    const float* Wo    = (const float*)d_in[8];
    const float* bo    = (const float*)d_in[9];
    const float* gamma = (const float*)d_in[10];
    const float* beta  = (const float*)d_in[11];
    float* out = (float*)d_out;

    cudaFuncSetAttribute(out_kernel, cudaFuncAttributeMaxDynamicSharedMemorySize, OUT_SMEM);

    convw_kernel<<<256, 144>>>(Wq, Wk, Wv, Wo);
    proj_kernel<<<N_NODES / 32, 256>>>(s, v, bq, bk, bv);
    attn_kernel<<<dim3(N_NODES / 128, H), 256>>>();
    out_kernel<<<N_NODES / 16, 128, OUT_SMEM>>>(s, v, bo, gamma, beta, out);
}